// round 11
// baseline (speedup 1.0000x reference)
#include <cuda_runtime.h>
#include <cstdint>
#include <cstddef>
#include <math.h>

#define NMAX 204800
#define GMAX 512

// ---- scratch (no allocations allowed) ----
__device__ __align__(16) float g_xW[(size_t)NMAX * 64]; // per-vertex x @ We1[:128] (raw)
__device__ __align__(16) int   g_mink[(size_t)NMAX * 8];
__device__ __align__(16) int   g_maxk[(size_t)NMAX * 8];
__device__ float g_Sfv[GMAX * 8];
__device__ float g_Smin[GMAX * 8];
__device__ float g_Smax[GMAX * 8];
__device__ float g_h[GMAX * 64];
__device__ float g_bn[128];

__device__ __forceinline__ float sigmoidf_(float x) {
    return 1.0f / (1.0f + __expf(-x));
}

__device__ __forceinline__ unsigned long long pack2(float lo, float hi) {
    unsigned long long r;
    asm("mov.b64 %0, {%1, %2};" : "=l"(r) : "f"(lo), "f"(hi));
    return r;
}
__device__ __forceinline__ void unpack2(unsigned long long v, float& lo, float& hi) {
    asm("mov.b64 {%0, %1}, %2;" : "=f"(lo), "=f"(hi) : "l"(v));
}
__device__ __forceinline__ unsigned long long ffma2(unsigned long long a,
                                                    unsigned long long b,
                                                    unsigned long long c) {
    unsigned long long d;
    asm("fma.rn.f32x2 %0, %1, %2, %3;" : "=l"(d) : "l"(a), "l"(b), "l"(c));
    return d;
}

__device__ __forceinline__ void cp_async16(unsigned dst, const void* src, int nbytes) {
    asm volatile("cp.async.cg.shared.global [%0], [%1], 16, %2;"
                 :: "r"(dst), "l"(src), "r"(nbytes));
}
#define CP_COMMIT() asm volatile("cp.async.commit_group;" ::: "memory")
#define CP_WAIT0()  asm volatile("cp.async.wait_group 0;" ::: "memory")

// init sentinels + Sfv
__global__ void init_kernel(int n8, int g8) {
    int i = blockIdx.x * blockDim.x + threadIdx.x;
    if (i < n8) { g_mink[i] = 0x7f800000; g_maxk[i] = 0; }
    if (i < g8) g_Sfv[i] = 0.0f;
}

// no-op spacers so ncu's fixed capture slot (4th launch) lands on vertex_kernel
__global__ void spacer_kernel() {}
__global__ void spacer2_kernel() {}

// ---------------------------------------------------------------------------
// Persistent vertex kernel: FFMA2 GEMM, cp.async double-buffered tiles.
// R11: 1024 threads = 16 warp PAIRS. Pair p owns rows m0=p*8 (tile 8Mx4N,
// R9's optimal wf/FFMA2 ratio); the two warps of a pair split k (64 each),
// combining partial accs through smem. 8 warps/SMSP for latency hiding at
// R9's shared-memory traffic level.
// ---------------------------------------------------------------------------
#define XS_STRIDE 132
#define XS_FLOATS (128 * XS_STRIDE)      // 16896
#define W_OFF     (2 * XS_FLOATS)        // 33792
#define W2_OFF    (W_OFF + 16384)        // 50176
#define B1_OFF    (W2_OFF + 512)
#define B2_OFF    (B1_OFF + 64)
#define SMV_FLOATS (B2_OFF + 8)          // 50760 floats = 203040 B

__device__ __forceinline__ void prefetch_tile(const float* __restrict__ x,
                                              int v0, int N,
                                              unsigned xs_sm, int tid) {
#pragma unroll
    for (int i = 0; i < 4; ++i) {
        int c = tid + i * 1024;          // 0..4095 chunk id
        int row = c >> 5, col4 = c & 31;
        unsigned dst = xs_sm + (unsigned)(row * XS_STRIDE + col4 * 4) * 4u;
        const float* src = x + (size_t)(v0 + row) * 128 + col4 * 4;
        int nb = (v0 + row < N) ? 16 : 0;   // zero-fill OOB rows
        cp_async16(dst, src, nb);
    }
}

__global__ __launch_bounds__(1024) void vertex_kernel(
    const float* __restrict__ x, const int* __restrict__ batch,
    const float* __restrict__ W1, const float* __restrict__ b1,
    const float* __restrict__ W2, const float* __restrict__ b2,
    const float* __restrict__ We1, int N, int tiles)
{
    extern __shared__ float sm[];
    float* Wsm = sm + W_OFF;
    float* W2s = sm + W2_OFF;
    float* b1s = sm + B1_OFF;
    float* b2s = sm + B2_OFF;

    const int tid = threadIdx.x;
    const unsigned sm_base = (unsigned)__cvta_generic_to_shared(sm);

    // ---- stage weights once ----
    for (int i = tid; i < 16384; i += 1024) {
        int k = i >> 7, n = i & 127;
        Wsm[i] = (n < 64) ? W1[k * 64 + n] : We1[k * 64 + (n - 64)];
    }
    if (tid < 512) W2s[tid] = W2[tid];
    if (tid < 64) b1s[tid] = b1[tid];
    if (tid < 8)  b2s[tid] = b2[tid];

    const int stride = gridDim.x;
    int pp = 0;
    if ((int)blockIdx.x < tiles)
        prefetch_tile(x, blockIdx.x * 128, N, sm_base, tid);
    CP_COMMIT();
    __syncthreads();   // weights + first-tile issue ordering

    const int tx   = tid & 31;        // lane -> N chunk (32 x 4 cols)
    const int w    = tid >> 5;        // warp id 0..31
    const int half = w & 1;           // k-half
    const int p    = w >> 1;          // pair id 0..15
    const int m0   = p * 8, n0 = tx * 4;
    const int k0   = half * 64;       // this warp's k range [k0, k0+64)

    for (int t = blockIdx.x; t < tiles; t += stride) {
        CP_WAIT0();
        __syncthreads();   // xs[pp] ready for everyone; prior epilogue done

        int tn = t + stride;
        if (tn < tiles)
            prefetch_tile(x, tn * 128, N,
                          sm_base + (unsigned)((pp ^ 1) * XS_FLOATS) * 4u, tid);
        CP_COMMIT();

        float* xs   = sm + pp * XS_FLOATS;
        float* hbuf = xs;                   // reused after k-loop
        const int v0 = t * 128;

        unsigned long long acc[8][2];
#pragma unroll
        for (int mi = 0; mi < 8; ++mi) { acc[mi][0] = 0ULL; acc[mi][1] = 0ULL; }

#pragma unroll 2
        for (int kq = 0; kq < 64; kq += 4) {
            const int k4 = k0 + kq;
            // hoist W for this k4 (4 kk x packed pair)
            unsigned long long wp[4][2];
#pragma unroll
            for (int kk = 0; kk < 4; ++kk) {
                float4 wa = *reinterpret_cast<const float4*>(
                    Wsm + ((k4 + kk) << 7) + n0);       // unique per lane
                wp[kk][0] = pack2(wa.x, wa.y);
                wp[kk][1] = pack2(wa.z, wa.w);
            }
            // two mi-groups of 4 to bound live registers
#pragma unroll
            for (int g = 0; g < 2; ++g) {
                float4 xr[4];
#pragma unroll
                for (int q = 0; q < 4; ++q)
                    xr[q] = *reinterpret_cast<const float4*>(
                        xs + (m0 + g * 4 + q) * XS_STRIDE + k4);  // warp-broadcast
#pragma unroll
                for (int kk = 0; kk < 4; ++kk) {
#pragma unroll
                    for (int q = 0; q < 4; ++q) {
                        int mi = g * 4 + q;
                        float xv = (kk == 0) ? xr[q].x
                                 : (kk == 1) ? xr[q].y
                                 : (kk == 2) ? xr[q].z : xr[q].w;
                        unsigned long long xx = pack2(xv, xv);
                        acc[mi][0] = ffma2(xx, wp[kk][0], acc[mi][0]);
                        acc[mi][1] = ffma2(xx, wp[kk][1], acc[mi][1]);
                    }
                }
            }
        }
        __syncthreads();   // all reads of xs[pp] done before hbuf overwrite

        // ---- combine k-halves through hbuf ----
        if (half == 1) {
#pragma unroll
            for (int mi = 0; mi < 8; ++mi) {
                float l0, h0, l1, h1;
                unpack2(acc[mi][0], l0, h0);
                unpack2(acc[mi][1], l1, h1);
                *reinterpret_cast<float4*>(hbuf + (m0 + mi) * XS_STRIDE + n0) =
                    make_float4(l0, h0, l1, h1);
            }
        }
        __syncthreads();

        if (half == 0) {
#pragma unroll
            for (int mi = 0; mi < 8; ++mi) {
                float4 o = *reinterpret_cast<const float4*>(
                    hbuf + (m0 + mi) * XS_STRIDE + n0);
                float l0, h0, l1, h1;
                unpack2(acc[mi][0], l0, h0);
                unpack2(acc[mi][1], l1, h1);
                l0 += o.x; h0 += o.y; l1 += o.z; h1 += o.w;
                if (tx < 16) {
                    float* dst = hbuf + (m0 + mi) * XS_STRIDE + n0;
                    dst[0] = l0; dst[1] = h0; dst[2] = l1; dst[3] = h1;
                } else {
                    int v = v0 + m0 + mi;
                    if (v < N)
                        *reinterpret_cast<float4*>(g_xW + (size_t)v * 64 + (n0 - 64)) =
                            make_float4(l0, h0, l1, h1);
                }
            }
        }
        __syncthreads();

        // fv epilogue: one vertex per thread (tid<128)
        if (tid < 128) {
            int v = v0 + tid;
            bool valid = (v < N);
            float a8[8];
#pragma unroll
            for (int f = 0; f < 8; ++f) a8[f] = b2s[f];
            const float* hr = hbuf + tid * XS_STRIDE;
#pragma unroll 4
            for (int k = 0; k < 64; ++k) {
                float hv = fmaxf(hr[k] + b1s[k], 0.0f);
#pragma unroll
                for (int f = 0; f < 8; ++f) a8[f] = fmaf(hv, W2s[k * 8 + f], a8[f]);
            }
#pragma unroll
            for (int f = 0; f < 8; ++f) a8[f] = valid ? sigmoidf_(a8[f]) : 0.0f;

            const unsigned m = 0xffffffffu;
            int lane = tid & 31;
            int gidx = batch[valid ? v : (N - 1)];
            int gl0  = __shfl_sync(m, gidx, 0);
            bool uni = __all_sync(m, gidx == gl0);
            if (uni) {
#pragma unroll
                for (int f = 0; f < 8; ++f) {
                    float s = a8[f];
                    s += __shfl_xor_sync(m, s, 16);
                    s += __shfl_xor_sync(m, s, 8);
                    s += __shfl_xor_sync(m, s, 4);
                    s += __shfl_xor_sync(m, s, 2);
                    s += __shfl_xor_sync(m, s, 1);
                    if (lane == 0) atomicAdd(&g_Sfv[gl0 * 8 + f], s);
                }
            } else if (valid) {
#pragma unroll
                for (int f = 0; f < 8; ++f) atomicAdd(&g_Sfv[gidx * 8 + f], a8[f]);
            }
        }
        pp ^= 1;
    }
}

// ---------------------------------------------------------------------------
// Edge kernel: 8 lanes cooperate per edge; h folded into fe (low live regs).
// ---------------------------------------------------------------------------
__global__ __launch_bounds__(256) void edge_kernel(
    const float* __restrict__ pos, const int* __restrict__ ei,
    const float* __restrict__ We1, const float* __restrict__ be1,
    const float* __restrict__ We2, const float* __restrict__ be2, int E)
{
    __shared__ __align__(16) float w1l[64];
    __shared__ __align__(16) float be1s[64];
    __shared__ float We2s[512];
    __shared__ float be2s[8];

    const int tid = threadIdx.x;
    for (int i = tid; i < 64; i += 256) { w1l[i] = We1[8192 + i]; be1s[i] = be1[i]; }
    for (int i = tid; i < 512; i += 256) We2s[i] = We2[i];
    if (tid < 8) be2s[tid] = be2[tid];
    __syncthreads();

    const int l = tid & 7;
    const int j0 = l * 8;
    const int egrp = (blockIdx.x * 256 + tid) >> 3;
    const int estride = (gridDim.x * 256) >> 3;
    const unsigned fullm = 0xffffffffu;

    for (int e = egrp; e < E; e += estride) {
        int s = ei[e], d = ei[E + e];
        float dx = pos[s * 3 + 0] - pos[d * 3 + 0];
        float dy = pos[s * 3 + 1] - pos[d * 3 + 1];
        float dz = pos[s * 3 + 2] - pos[d * 3 + 2];
        float dist = sqrtf(dx * dx + dy * dy + dz * dz);

        const float4* xs4 = reinterpret_cast<const float4*>(g_xW + (size_t)s * 64 + j0);
        const float4* xd4 = reinterpret_cast<const float4*>(g_xW + (size_t)d * 64 + j0);

        float fe[8];
#pragma unroll
        for (int f = 0; f < 8; ++f) fe[f] = 0.0f;

#pragma unroll
        for (int q = 0; q < 2; ++q) {
            float4 aa = xs4[q], bb = xd4[q];
            float4 wl = *reinterpret_cast<const float4*>(w1l + j0 + 4 * q);
            float4 bv = *reinterpret_cast<const float4*>(be1s + j0 + 4 * q);
            float h0 = fmaxf(fmaf(dist, wl.x, aa.x + bb.x) + bv.x, 0.0f);
            float h1 = fmaxf(fmaf(dist, wl.y, aa.y + bb.y) + bv.y, 0.0f);
            float h2 = fmaxf(fmaf(dist, wl.z, aa.z + bb.z) + bv.z, 0.0f);
            float h3 = fmaxf(fmaf(dist, wl.w, aa.w + bb.w) + bv.w, 0.0f);
            const float* w0r = We2s + (j0 + 4 * q) * 8;
#pragma unroll
            for (int f = 0; f < 8; ++f) {
                float acc = fmaf(h0, w0r[f], fe[f]);
                acc = fmaf(h1, w0r[8 + f], acc);
                acc = fmaf(h2, w0r[16 + f], acc);
                fe[f] = fmaf(h3, w0r[24 + f], acc);
            }
        }
#pragma unroll
        for (int f = 0; f < 8; ++f) {
            float v = fe[f];
            v += __shfl_xor_sync(fullm, v, 4);
            v += __shfl_xor_sync(fullm, v, 2);
            v += __shfl_xor_sync(fullm, v, 1);
            fe[f] = v;
        }
        int key = __float_as_int(sigmoidf_(fe[l] + be2s[l]));
        atomicMin(g_mink + (size_t)s * 8 + l, key);
        atomicMin(g_mink + (size_t)d * 8 + l, key);
        atomicMax(g_maxk + (size_t)s * 8 + l, key);
        atomicMax(g_maxk + (size_t)d * 8 + l, key);
    }
}

// ---------------------------------------------------------------------------
// Per-graph vertex reduce: fixup sentinels -> 1.0, sum dmin/dmax per graph
// ---------------------------------------------------------------------------
__global__ __launch_bounds__(256) void vreduce_kernel(const int* __restrict__ vs)
{
    __shared__ float rn[8], rx[8];
    const int tid = threadIdx.x, g = blockIdx.x;
    const int v0 = vs[g], v1 = vs[g + 1];
    if (tid < 8) { rn[tid] = 0.0f; rx[tid] = 0.0f; }
    __syncthreads();

    float ln[8], lx[8];
#pragma unroll
    for (int f = 0; f < 8; ++f) { ln[f] = 0.0f; lx[f] = 0.0f; }
    for (int v = v0 + tid; v < v1; v += 256) {
        const int4* mn = reinterpret_cast<const int4*>(g_mink + (size_t)v * 8);
        const int4* mx = reinterpret_cast<const int4*>(g_maxk + (size_t)v * 8);
        int4 a = mn[0], b = mn[1], c = mx[0], d = mx[1];
        ln[0] += (a.x == 0x7f800000) ? 1.0f : __int_as_float(a.x);
        ln[1] += (a.y == 0x7f800000) ? 1.0f : __int_as_float(a.y);
        ln[2] += (a.z == 0x7f800000) ? 1.0f : __int_as_float(a.z);
        ln[3] += (a.w == 0x7f800000) ? 1.0f : __int_as_float(a.w);
        ln[4] += (b.x == 0x7f800000) ? 1.0f : __int_as_float(b.x);
        ln[5] += (b.y == 0x7f800000) ? 1.0f : __int_as_float(b.y);
        ln[6] += (b.z == 0x7f800000) ? 1.0f : __int_as_float(b.z);
        ln[7] += (b.w == 0x7f800000) ? 1.0f : __int_as_float(b.w);
        lx[0] += (c.x == 0) ? 1.0f : __int_as_float(c.x);
        lx[1] += (c.y == 0) ? 1.0f : __int_as_float(c.y);
        lx[2] += (c.z == 0) ? 1.0f : __int_as_float(c.z);
        lx[3] += (c.w == 0) ? 1.0f : __int_as_float(c.w);
        lx[4] += (d.x == 0) ? 1.0f : __int_as_float(d.x);
        lx[5] += (d.y == 0) ? 1.0f : __int_as_float(d.y);
        lx[6] += (d.z == 0) ? 1.0f : __int_as_float(d.z);
        lx[7] += (d.w == 0) ? 1.0f : __int_as_float(d.w);
    }
    const unsigned m = 0xffffffffu;
    int lane = tid & 31;
#pragma unroll
    for (int f = 0; f < 8; ++f) {
        float s = ln[f];
        s += __shfl_xor_sync(m, s, 16); s += __shfl_xor_sync(m, s, 8);
        s += __shfl_xor_sync(m, s, 4);  s += __shfl_xor_sync(m, s, 2);
        s += __shfl_xor_sync(m, s, 1);
        if (lane == 0) atomicAdd(&rn[f], s);
        float t = lx[f];
        t += __shfl_xor_sync(m, t, 16); t += __shfl_xor_sync(m, t, 8);
        t += __shfl_xor_sync(m, t, 4);  t += __shfl_xor_sync(m, t, 2);
        t += __shfl_xor_sync(m, t, 1);
        if (lane == 0) atomicAdd(&rx[f], t);
    }
    __syncthreads();
    if (tid < 8) { g_Smin[g * 8 + tid] = rn[tid]; g_Smax[g * 8 + tid] = rx[tid]; }
}

// h = x0 + x1 (pre-BN)
__global__ void f1_kernel(const float* __restrict__ Wd0, const float* __restrict__ bd0,
                          const float* __restrict__ Wd1, const float* __restrict__ bd1,
                          const int* __restrict__ vs, const int* __restrict__ es)
{
    int g = blockIdx.x, o = threadIdx.x;
    float a = 0.0f;
#pragma unroll
    for (int f = 0; f < 8; ++f) {
        float sf = g_Sfv[g * 8 + f];
        float sx = g_Smax[g * 8 + f];
        float sn = g_Smin[g * 8 + f];
        a = fmaf(sf, Wd0[(4 * f + 1) * 64 + o], a);
        a = fmaf(sx, Wd0[(4 * f + 2) * 64 + o], a);
        a = fmaf(sn, Wd0[(4 * f + 3) * 64 + o], a);
    }
    int nv = vs[g + 1] - vs[g];
    int ne = es[g + 1] - es[g];
    float x0 = a / (float)nv + bd0[o];
    float x1 = (ne - (nv - 1) > 0)
                   ? (Wd1[64 + o] + Wd1[128 + o] + Wd1[192 + o] + bd1[o])
                   : 0.0f;
    g_h[g * 64 + o] = x0 + x1;
}

// BatchNorm stats (two-pass)
__global__ void bn_kernel(int G)
{
    __shared__ float ps[512];
    __shared__ float mu_s[64];
    int t = threadIdx.x, o = t & 63, grp = t >> 6;
    float s = 0.0f;
    for (int r = grp; r < G; r += 8) s += g_h[r * 64 + o];
    ps[t] = s;
    __syncthreads();
    if (t < 64) {
        float S = 0.0f;
        for (int k = 0; k < 8; ++k) S += ps[k * 64 + o];
        mu_s[o] = S / (float)G;
    }
    __syncthreads();
    float mu = mu_s[o];
    s = 0.0f;
    for (int r = grp; r < G; r += 8) { float d = g_h[r * 64 + o] - mu; s = fmaf(d, d, s); }
    ps[t] = s;
    __syncthreads();
    if (t < 64) {
        float S = 0.0f;
        for (int k = 0; k < 8; ++k) S += ps[k * 64 + o];
        g_bn[o] = mu_s[o];
        g_bn[64 + o] = rsqrtf(S / (float)G + 1e-5f);
    }
}

// normalize + out MLP
__global__ __launch_bounds__(1024) void out_kernel(
    const float* __restrict__ gamma, const float* __restrict__ beta,
    const float* __restrict__ Wo1, const float* __restrict__ bo1,
    const float* __restrict__ Wo2, const float* __restrict__ bo2,
    float* __restrict__ out, int G)
{
    __shared__ float hn[16][64];
    __shared__ float t1[16][64];
    int t = threadIdx.x, gl = t >> 6, o = t & 63;
    int g = blockIdx.x * 16 + gl;
    float v = 0.0f;
    if (g < G) v = (g_h[g * 64 + o] - g_bn[o]) * g_bn[64 + o] * gamma[o] + beta[o];
    hn[gl][o] = v;
    __syncthreads();
    float a = bo1[o];
#pragma unroll 8
    for (int k = 0; k < 64; ++k) a = fmaf(hn[gl][k], Wo1[k * 64 + o], a);
    t1[gl][o] = fmaxf(a, 0.0f);
    __syncthreads();
    float b = bo2[o];
#pragma unroll 8
    for (int k = 0; k < 64; ++k) b = fmaf(t1[gl][k], Wo2[k * 64 + o], b);
    if (g < G) out[g * 64 + o] = b;
}

extern "C" void kernel_launch(void* const* d_in, const int* in_sizes, int n_in,
                              void* d_out, int out_size)
{
    const float* x     = (const float*)d_in[0];
    const float* pos   = (const float*)d_in[1];
    const int*   ei    = (const int*)d_in[2];
    const int*   vs    = (const int*)d_in[3];
    const int*   es    = (const int*)d_in[4];
    const int*   batch = (const int*)d_in[5];
    const float* W1  = (const float*)d_in[6];
    const float* b1  = (const float*)d_in[7];
    const float* W2  = (const float*)d_in[8];
    const float* b2  = (const float*)d_in[9];
    const float* We1 = (const float*)d_in[10];
    const float* be1 = (const float*)d_in[11];
    const float* We2 = (const float*)d_in[12];
    const float* be2 = (const float*)d_in[13];
    const float* Wd0 = (const float*)d_in[14];
    const float* bd0 = (const float*)d_in[15];
    const float* Wd1 = (const float*)d_in[16];
    const float* bd1 = (const float*)d_in[17];
    const float* gm  = (const float*)d_in[18];
    const float* bt  = (const float*)d_in[19];
    const float* Wo1 = (const float*)d_in[20];
    const float* bo1 = (const float*)d_in[21];
    const float* Wo2 = (const float*)d_in[22];
    const float* bo2 = (const float*)d_in[23];

    int N = in_sizes[0] / 128;
    int E = in_sizes[2] / 2;
    int G = out_size / 64;
    int tiles = (N + 127) / 128;

    init_kernel<<<(N * 8 + 255) / 256, 256>>>(N * 8, G * 8);   // launch 1
    spacer_kernel<<<1, 32>>>();                                 // launch 2
    spacer2_kernel<<<1, 32>>>();                                // launch 3

    size_t smv = (size_t)SMV_FLOATS * sizeof(float);
    cudaFuncSetAttribute(vertex_kernel, cudaFuncAttributeMaxDynamicSharedMemorySize, (int)smv);
    vertex_kernel<<<148, 1024, smv>>>(x, batch, W1, b1, W2, b2, We1, N, tiles); // launch 4 (ncu slot)

    edge_kernel<<<1024, 256>>>(pos, ei, We1, be1, We2, be2, E); // launch 5
    vreduce_kernel<<<G, 256>>>(vs);
    f1_kernel<<<G, 64>>>(Wd0, bd0, Wd1, bd1, vs, es);
    bn_kernel<<<1, 512>>>(G);
    out_kernel<<<(G + 15) / 16, 1024>>>(gm, bt, Wo1, bo1, Wo2, bo2, (float*)d_out, G);
}

// round 12
// speedup vs baseline: 1.2890x; 1.2890x over previous
#include <cuda_runtime.h>
#include <cstdint>
#include <cstddef>
#include <math.h>

#define NMAX 204800
#define GMAX 512

// ---- scratch (no allocations allowed) ----
__device__ __align__(16) float g_xW[(size_t)NMAX * 64]; // per-vertex x @ We1[:128] (raw)
__device__ __align__(16) int   g_mink[(size_t)NMAX * 8];
__device__ __align__(16) int   g_maxk[(size_t)NMAX * 8];
__device__ float g_Sfv[GMAX * 8];
__device__ float g_Smin[GMAX * 8];
__device__ float g_Smax[GMAX * 8];
__device__ float g_h[GMAX * 64];
__device__ float g_bn[128];

__device__ __forceinline__ float sigmoidf_(float x) {
    return 1.0f / (1.0f + __expf(-x));
}

__device__ __forceinline__ unsigned long long pack2(float lo, float hi) {
    unsigned long long r;
    asm("mov.b64 %0, {%1, %2};" : "=l"(r) : "f"(lo), "f"(hi));
    return r;
}
__device__ __forceinline__ void unpack2(unsigned long long v, float& lo, float& hi) {
    asm("mov.b64 {%0, %1}, %2;" : "=f"(lo), "=f"(hi) : "l"(v));
}
__device__ __forceinline__ unsigned long long ffma2(unsigned long long a,
                                                    unsigned long long b,
                                                    unsigned long long c) {
    unsigned long long d;
    asm("fma.rn.f32x2 %0, %1, %2, %3;" : "=l"(d) : "l"(a), "l"(b), "l"(c));
    return d;
}

__device__ __forceinline__ void cp_async16(unsigned dst, const void* src, int nbytes) {
    asm volatile("cp.async.cg.shared.global [%0], [%1], 16, %2;"
                 :: "r"(dst), "l"(src), "r"(nbytes));
}
#define CP_COMMIT() asm volatile("cp.async.commit_group;" ::: "memory")
#define CP_WAIT0()  asm volatile("cp.async.wait_group 0;" ::: "memory")

// init sentinels + Sfv
__global__ void init_kernel(int n8, int g8) {
    int i = blockIdx.x * blockDim.x + threadIdx.x;
    if (i < n8) { g_mink[i] = 0x7f800000; g_maxk[i] = 0; }
    if (i < g8) g_Sfv[i] = 0.0f;
}

// no-op spacer so ncu's fixed capture slot (4th launch) lands on edge_kernel
__global__ void spacer_kernel() {}

// ---------------------------------------------------------------------------
// Persistent vertex kernel (exact R9 config: best measured, 179us):
// 512 threads, tile 8Mx4N, tx=lane (unique W LDS.128), m0=warp*8 (broadcast x).
// ---------------------------------------------------------------------------
#define XS_STRIDE 132
#define XS_FLOATS (128 * XS_STRIDE)      // 16896
#define W_OFF     (2 * XS_FLOATS)        // 33792
#define W2_OFF    (W_OFF + 16384)        // 50176
#define B1_OFF    (W2_OFF + 512)
#define B2_OFF    (B1_OFF + 64)
#define SMV_FLOATS (B2_OFF + 8)          // 50760 floats = 203040 B

__device__ __forceinline__ void prefetch_tile(const float* __restrict__ x,
                                              int v0, int N,
                                              unsigned xs_sm, int tid) {
#pragma unroll
    for (int i = 0; i < 8; ++i) {
        int c = tid + i * 512;           // 0..4095 chunk id
        int row = c >> 5, col4 = c & 31;
        unsigned dst = xs_sm + (unsigned)(row * XS_STRIDE + col4 * 4) * 4u;
        const float* src = x + (size_t)(v0 + row) * 128 + col4 * 4;
        int nb = (v0 + row < N) ? 16 : 0;   // zero-fill OOB rows
        cp_async16(dst, src, nb);
    }
}

__global__ __launch_bounds__(512) void vertex_kernel(
    const float* __restrict__ x, const int* __restrict__ batch,
    const float* __restrict__ W1, const float* __restrict__ b1,
    const float* __restrict__ W2, const float* __restrict__ b2,
    const float* __restrict__ We1, int N, int tiles)
{
    extern __shared__ float sm[];
    float* Wsm = sm + W_OFF;
    float* W2s = sm + W2_OFF;
    float* b1s = sm + B1_OFF;
    float* b2s = sm + B2_OFF;

    const int tid = threadIdx.x;
    const unsigned sm_base = (unsigned)__cvta_generic_to_shared(sm);

    for (int i = tid; i < 16384; i += 512) {
        int k = i >> 7, n = i & 127;
        Wsm[i] = (n < 64) ? W1[k * 64 + n] : We1[k * 64 + (n - 64)];
    }
    if (tid < 512) W2s[tid] = W2[tid];
    if (tid < 64) b1s[tid] = b1[tid];
    if (tid < 8)  b2s[tid] = b2[tid];

    const int stride = gridDim.x;
    int pp = 0;
    if ((int)blockIdx.x < tiles)
        prefetch_tile(x, blockIdx.x * 128, N, sm_base, tid);
    CP_COMMIT();
    __syncthreads();

    const int tx = tid & 31;          // lane -> N chunk (32 x 4 cols)
    const int ty = tid >> 5;          // warp -> M chunk (16 x 8 rows)
    const int m0 = ty * 8, n0 = tx * 4;

    for (int t = blockIdx.x; t < tiles; t += stride) {
        CP_WAIT0();
        __syncthreads();

        int tn = t + stride;
        if (tn < tiles)
            prefetch_tile(x, tn * 128, N,
                          sm_base + (unsigned)((pp ^ 1) * XS_FLOATS) * 4u, tid);
        CP_COMMIT();

        float* xs   = sm + pp * XS_FLOATS;
        float* hbuf = xs;
        const int v0 = t * 128;

        unsigned long long acc[8][2];
#pragma unroll
        for (int mi = 0; mi < 8; ++mi) { acc[mi][0] = 0ULL; acc[mi][1] = 0ULL; }

#pragma unroll 2
        for (int k4 = 0; k4 < 128; k4 += 4) {
            float4 xr[8];
#pragma unroll
            for (int mi = 0; mi < 8; ++mi)
                xr[mi] = *reinterpret_cast<const float4*>(
                    xs + (m0 + mi) * XS_STRIDE + k4);   // warp-broadcast
#pragma unroll
            for (int kk = 0; kk < 4; ++kk) {
                float4 wa = *reinterpret_cast<const float4*>(
                    Wsm + ((k4 + kk) << 7) + n0);       // unique per lane
                unsigned long long w0 = pack2(wa.x, wa.y);
                unsigned long long w1p = pack2(wa.z, wa.w);
#pragma unroll
                for (int mi = 0; mi < 8; ++mi) {
                    float xv = (kk == 0) ? xr[mi].x
                             : (kk == 1) ? xr[mi].y
                             : (kk == 2) ? xr[mi].z : xr[mi].w;
                    unsigned long long xx = pack2(xv, xv);
                    acc[mi][0] = ffma2(xx, w0,  acc[mi][0]);
                    acc[mi][1] = ffma2(xx, w1p, acc[mi][1]);
                }
            }
        }
        __syncthreads();

        if (tx < 16) {
#pragma unroll
            for (int mi = 0; mi < 8; ++mi) {
                float* dst = hbuf + (m0 + mi) * XS_STRIDE + n0;
                float l0, h0, l1, h1;
                unpack2(acc[mi][0], l0, h0);
                unpack2(acc[mi][1], l1, h1);
                dst[0] = l0; dst[1] = h0; dst[2] = l1; dst[3] = h1;
            }
        } else {
#pragma unroll
            for (int mi = 0; mi < 8; ++mi) {
                int v = v0 + m0 + mi;
                if (v < N) {
                    float l0, h0, l1, h1;
                    unpack2(acc[mi][0], l0, h0);
                    unpack2(acc[mi][1], l1, h1);
                    *reinterpret_cast<float4*>(g_xW + (size_t)v * 64 + (n0 - 64)) =
                        make_float4(l0, h0, l1, h1);
                }
            }
        }
        __syncthreads();

        if (tid < 128) {
            int v = v0 + tid;
            bool valid = (v < N);
            float a8[8];
#pragma unroll
            for (int f = 0; f < 8; ++f) a8[f] = b2s[f];
            const float* hr = hbuf + tid * XS_STRIDE;
#pragma unroll 4
            for (int k = 0; k < 64; ++k) {
                float hv = fmaxf(hr[k] + b1s[k], 0.0f);
#pragma unroll
                for (int f = 0; f < 8; ++f) a8[f] = fmaf(hv, W2s[k * 8 + f], a8[f]);
            }
#pragma unroll
            for (int f = 0; f < 8; ++f) a8[f] = valid ? sigmoidf_(a8[f]) : 0.0f;

            const unsigned m = 0xffffffffu;
            int lane = tid & 31;
            int gidx = batch[valid ? v : (N - 1)];
            int gl0  = __shfl_sync(m, gidx, 0);
            bool uni = __all_sync(m, gidx == gl0);
            if (uni) {
#pragma unroll
                for (int f = 0; f < 8; ++f) {
                    float s = a8[f];
                    s += __shfl_xor_sync(m, s, 16);
                    s += __shfl_xor_sync(m, s, 8);
                    s += __shfl_xor_sync(m, s, 4);
                    s += __shfl_xor_sync(m, s, 2);
                    s += __shfl_xor_sync(m, s, 1);
                    if (lane == 0) atomicAdd(&g_Sfv[gl0 * 8 + f], s);
                }
            } else if (valid) {
#pragma unroll
                for (int f = 0; f < 8; ++f) atomicAdd(&g_Sfv[gidx * 8 + f], a8[f]);
            }
        }
        pp ^= 1;
    }
}

// ---------------------------------------------------------------------------
// Edge kernel (R12): 16 lanes per edge, 4 channels each — low register
// pressure for occupancy, fully coalesced gathers, 2 atomics per lane.
// ---------------------------------------------------------------------------
__global__ __launch_bounds__(256) void edge_kernel(
    const float* __restrict__ pos, const int* __restrict__ ei,
    const float* __restrict__ We1, const float* __restrict__ be1,
    const float* __restrict__ We2, const float* __restrict__ be2, int E)
{
    __shared__ __align__(16) float w1l[64];
    __shared__ __align__(16) float be1s[64];
    __shared__ float We2s[512];
    __shared__ float be2s[8];

    const int tid = threadIdx.x;
    for (int i = tid; i < 64; i += 256) { w1l[i] = We1[8192 + i]; be1s[i] = be1[i]; }
    for (int i = tid; i < 512; i += 256) We2s[i] = We2[i];
    if (tid < 8) be2s[tid] = be2[tid];
    __syncthreads();

    const int l  = tid & 15;               // lane within 16-group
    const int j0 = l * 4;                  // this lane's 4 channels of j
    const int grp = tid >> 4;              // 16 groups per block
    const unsigned fullm = 0xffffffffu;

    for (int e0 = blockIdx.x * 16; e0 < E; e0 += gridDim.x * 16) {
        int e = e0 + grp;
        bool active = (e < E);
        int eidx = active ? e : (E - 1);
        int s = ei[eidx], d = ei[E + eidx];

        float dx = pos[s * 3 + 0] - pos[d * 3 + 0];
        float dy = pos[s * 3 + 1] - pos[d * 3 + 1];
        float dz = pos[s * 3 + 2] - pos[d * 3 + 2];
        float dist = sqrtf(dx * dx + dy * dy + dz * dz);

        float4 aa = *reinterpret_cast<const float4*>(g_xW + (size_t)s * 64 + j0);
        float4 bb = *reinterpret_cast<const float4*>(g_xW + (size_t)d * 64 + j0);
        float4 wl = *reinterpret_cast<const float4*>(w1l + j0);
        float4 bv = *reinterpret_cast<const float4*>(be1s + j0);

        float h0 = fmaxf(fmaf(dist, wl.x, aa.x + bb.x) + bv.x, 0.0f);
        float h1 = fmaxf(fmaf(dist, wl.y, aa.y + bb.y) + bv.y, 0.0f);
        float h2 = fmaxf(fmaf(dist, wl.z, aa.z + bb.z) + bv.z, 0.0f);
        float h3 = fmaxf(fmaf(dist, wl.w, aa.w + bb.w) + bv.w, 0.0f);

        float fe[8];
        const float* w0r = We2s + j0 * 8;
#pragma unroll
        for (int f = 0; f < 8; ++f) {
            float acc = h0 * w0r[f];
            acc = fmaf(h1, w0r[8 + f], acc);
            acc = fmaf(h2, w0r[16 + f], acc);
            fe[f] = fmaf(h3, w0r[24 + f], acc);
        }
        // reduce partial fe across the 16 lanes of this edge group
#pragma unroll
        for (int f = 0; f < 8; ++f) {
            float v = fe[f];
            v += __shfl_xor_sync(fullm, v, 8);
            v += __shfl_xor_sync(fullm, v, 4);
            v += __shfl_xor_sync(fullm, v, 2);
            v += __shfl_xor_sync(fullm, v, 1);
            fe[f] = v;
        }
        // lane l<8: channel l on vertex s; lane l>=8: channel l-8 on vertex d
        int c = l & 7;
        int vtx = (l < 8) ? s : d;
        int key = __float_as_int(sigmoidf_(fe[c] + be2s[c]));
        if (active) {
            atomicMin(g_mink + (size_t)vtx * 8 + c, key);
            atomicMax(g_maxk + (size_t)vtx * 8 + c, key);
        }
    }
}

// ---------------------------------------------------------------------------
// Per-graph vertex reduce: fixup sentinels -> 1.0, sum dmin/dmax per graph
// ---------------------------------------------------------------------------
__global__ __launch_bounds__(256) void vreduce_kernel(const int* __restrict__ vs)
{
    __shared__ float rn[8], rx[8];
    const int tid = threadIdx.x, g = blockIdx.x;
    const int v0 = vs[g], v1 = vs[g + 1];
    if (tid < 8) { rn[tid] = 0.0f; rx[tid] = 0.0f; }
    __syncthreads();

    float ln[8], lx[8];
#pragma unroll
    for (int f = 0; f < 8; ++f) { ln[f] = 0.0f; lx[f] = 0.0f; }
    for (int v = v0 + tid; v < v1; v += 256) {
        const int4* mn = reinterpret_cast<const int4*>(g_mink + (size_t)v * 8);
        const int4* mx = reinterpret_cast<const int4*>(g_maxk + (size_t)v * 8);
        int4 a = mn[0], b = mn[1], c = mx[0], d = mx[1];
        ln[0] += (a.x == 0x7f800000) ? 1.0f : __int_as_float(a.x);
        ln[1] += (a.y == 0x7f800000) ? 1.0f : __int_as_float(a.y);
        ln[2] += (a.z == 0x7f800000) ? 1.0f : __int_as_float(a.z);
        ln[3] += (a.w == 0x7f800000) ? 1.0f : __int_as_float(a.w);
        ln[4] += (b.x == 0x7f800000) ? 1.0f : __int_as_float(b.x);
        ln[5] += (b.y == 0x7f800000) ? 1.0f : __int_as_float(b.y);
        ln[6] += (b.z == 0x7f800000) ? 1.0f : __int_as_float(b.z);
        ln[7] += (b.w == 0x7f800000) ? 1.0f : __int_as_float(b.w);
        lx[0] += (c.x == 0) ? 1.0f : __int_as_float(c.x);
        lx[1] += (c.y == 0) ? 1.0f : __int_as_float(c.y);
        lx[2] += (c.z == 0) ? 1.0f : __int_as_float(c.z);
        lx[3] += (c.w == 0) ? 1.0f : __int_as_float(c.w);
        lx[4] += (d.x == 0) ? 1.0f : __int_as_float(d.x);
        lx[5] += (d.y == 0) ? 1.0f : __int_as_float(d.y);
        lx[6] += (d.z == 0) ? 1.0f : __int_as_float(d.z);
        lx[7] += (d.w == 0) ? 1.0f : __int_as_float(d.w);
    }
    const unsigned m = 0xffffffffu;
    int lane = tid & 31;
#pragma unroll
    for (int f = 0; f < 8; ++f) {
        float s = ln[f];
        s += __shfl_xor_sync(m, s, 16); s += __shfl_xor_sync(m, s, 8);
        s += __shfl_xor_sync(m, s, 4);  s += __shfl_xor_sync(m, s, 2);
        s += __shfl_xor_sync(m, s, 1);
        if (lane == 0) atomicAdd(&rn[f], s);
        float t = lx[f];
        t += __shfl_xor_sync(m, t, 16); t += __shfl_xor_sync(m, t, 8);
        t += __shfl_xor_sync(m, t, 4);  t += __shfl_xor_sync(m, t, 2);
        t += __shfl_xor_sync(m, t, 1);
        if (lane == 0) atomicAdd(&rx[f], t);
    }
    __syncthreads();
    if (tid < 8) { g_Smin[g * 8 + tid] = rn[tid]; g_Smax[g * 8 + tid] = rx[tid]; }
}

// h = x0 + x1 (pre-BN)
__global__ void f1_kernel(const float* __restrict__ Wd0, const float* __restrict__ bd0,
                          const float* __restrict__ Wd1, const float* __restrict__ bd1,
                          const int* __restrict__ vs, const int* __restrict__ es)
{
    int g = blockIdx.x, o = threadIdx.x;
    float a = 0.0f;
#pragma unroll
    for (int f = 0; f < 8; ++f) {
        float sf = g_Sfv[g * 8 + f];
        float sx = g_Smax[g * 8 + f];
        float sn = g_Smin[g * 8 + f];
        a = fmaf(sf, Wd0[(4 * f + 1) * 64 + o], a);
        a = fmaf(sx, Wd0[(4 * f + 2) * 64 + o], a);
        a = fmaf(sn, Wd0[(4 * f + 3) * 64 + o], a);
    }
    int nv = vs[g + 1] - vs[g];
    int ne = es[g + 1] - es[g];
    float x0 = a / (float)nv + bd0[o];
    float x1 = (ne - (nv - 1) > 0)
                   ? (Wd1[64 + o] + Wd1[128 + o] + Wd1[192 + o] + bd1[o])
                   : 0.0f;
    g_h[g * 64 + o] = x0 + x1;
}

// BatchNorm stats (two-pass)
__global__ void bn_kernel(int G)
{
    __shared__ float ps[512];
    __shared__ float mu_s[64];
    int t = threadIdx.x, o = t & 63, grp = t >> 6;
    float s = 0.0f;
    for (int r = grp; r < G; r += 8) s += g_h[r * 64 + o];
    ps[t] = s;
    __syncthreads();
    if (t < 64) {
        float S = 0.0f;
        for (int k = 0; k < 8; ++k) S += ps[k * 64 + o];
        mu_s[o] = S / (float)G;
    }
    __syncthreads();
    float mu = mu_s[o];
    s = 0.0f;
    for (int r = grp; r < G; r += 8) { float d = g_h[r * 64 + o] - mu; s = fmaf(d, d, s); }
    ps[t] = s;
    __syncthreads();
    if (t < 64) {
        float S = 0.0f;
        for (int k = 0; k < 8; ++k) S += ps[k * 64 + o];
        g_bn[o] = mu_s[o];
        g_bn[64 + o] = rsqrtf(S / (float)G + 1e-5f);
    }
}

// normalize + out MLP
__global__ __launch_bounds__(1024) void out_kernel(
    const float* __restrict__ gamma, const float* __restrict__ beta,
    const float* __restrict__ Wo1, const float* __restrict__ bo1,
    const float* __restrict__ Wo2, const float* __restrict__ bo2,
    float* __restrict__ out, int G)
{
    __shared__ float hn[16][64];
    __shared__ float t1[16][64];
    int t = threadIdx.x, gl = t >> 6, o = t & 63;
    int g = blockIdx.x * 16 + gl;
    float v = 0.0f;
    if (g < G) v = (g_h[g * 64 + o] - g_bn[o]) * g_bn[64 + o] * gamma[o] + beta[o];
    hn[gl][o] = v;
    __syncthreads();
    float a = bo1[o];
#pragma unroll 8
    for (int k = 0; k < 64; ++k) a = fmaf(hn[gl][k], Wo1[k * 64 + o], a);
    t1[gl][o] = fmaxf(a, 0.0f);
    __syncthreads();
    float b = bo2[o];
#pragma unroll 8
    for (int k = 0; k < 64; ++k) b = fmaf(t1[gl][k], Wo2[k * 64 + o], b);
    if (g < G) out[g * 64 + o] = b;
}

extern "C" void kernel_launch(void* const* d_in, const int* in_sizes, int n_in,
                              void* d_out, int out_size)
{
    const float* x     = (const float*)d_in[0];
    const float* pos   = (const float*)d_in[1];
    const int*   ei    = (const int*)d_in[2];
    const int*   vs    = (const int*)d_in[3];
    const int*   es    = (const int*)d_in[4];
    const int*   batch = (const int*)d_in[5];
    const float* W1  = (const float*)d_in[6];
    const float* b1  = (const float*)d_in[7];
    const float* W2  = (const float*)d_in[8];
    const float* b2  = (const float*)d_in[9];
    const float* We1 = (const float*)d_in[10];
    const float* be1 = (const float*)d_in[11];
    const float* We2 = (const float*)d_in[12];
    const float* be2 = (const float*)d_in[13];
    const float* Wd0 = (const float*)d_in[14];
    const float* bd0 = (const float*)d_in[15];
    const float* Wd1 = (const float*)d_in[16];
    const float* bd1 = (const float*)d_in[17];
    const float* gm  = (const float*)d_in[18];
    const float* bt  = (const float*)d_in[19];
    const float* Wo1 = (const float*)d_in[20];
    const float* bo1 = (const float*)d_in[21];
    const float* Wo2 = (const float*)d_in[22];
    const float* bo2 = (const float*)d_in[23];

    int N = in_sizes[0] / 128;
    int E = in_sizes[2] / 2;
    int G = out_size / 64;
    int tiles = (N + 127) / 128;

    init_kernel<<<(N * 8 + 255) / 256, 256>>>(N * 8, G * 8);   // launch 1
    spacer_kernel<<<1, 32>>>();                                 // launch 2

    size_t smv = (size_t)SMV_FLOATS * sizeof(float);
    cudaFuncSetAttribute(vertex_kernel, cudaFuncAttributeMaxDynamicSharedMemorySize, (int)smv);
    vertex_kernel<<<148, 512, smv>>>(x, batch, W1, b1, W2, b2, We1, N, tiles); // launch 3

    edge_kernel<<<2048, 256>>>(pos, ei, We1, be1, We2, be2, E); // launch 4 (ncu slot)
    vreduce_kernel<<<G, 256>>>(vs);
    f1_kernel<<<G, 64>>>(Wd0, bd0, Wd1, bd1, vs, es);
    bn_kernel<<<1, 512>>>(G);
    out_kernel<<<(G + 15) / 16, 1024>>>(gm, bt, Wo1, bo1, Wo2, bo2, (float*)d_out, G);
}

// round 13
// speedup vs baseline: 1.3731x; 1.0653x over previous
#include <cuda_runtime.h>
#include <cstdint>
#include <cstddef>
#include <math.h>

#define NMAX 204800
#define GMAX 512

// ---- scratch (no allocations allowed) ----
__device__ __align__(16) float g_xW[(size_t)NMAX * 64]; // per-vertex x @ We1[:128] (raw)
__device__ __align__(16) int   g_mink[(size_t)NMAX * 8];
__device__ __align__(16) int   g_maxk[(size_t)NMAX * 8];
__device__ float g_Sfv[GMAX * 8];
__device__ float g_Smin[GMAX * 8];
__device__ float g_Smax[GMAX * 8];
__device__ float g_h[GMAX * 64];
__device__ float g_bn[128];

__device__ __forceinline__ float sigmoidf_(float x) {
    return 1.0f / (1.0f + __expf(-x));
}

__device__ __forceinline__ unsigned long long pack2(float lo, float hi) {
    unsigned long long r;
    asm("mov.b64 %0, {%1, %2};" : "=l"(r) : "f"(lo), "f"(hi));
    return r;
}
__device__ __forceinline__ void unpack2(unsigned long long v, float& lo, float& hi) {
    asm("mov.b64 {%0, %1}, %2;" : "=f"(lo), "=f"(hi) : "l"(v));
}
__device__ __forceinline__ unsigned long long ffma2(unsigned long long a,
                                                    unsigned long long b,
                                                    unsigned long long c) {
    unsigned long long d;
    asm("fma.rn.f32x2 %0, %1, %2, %3;" : "=l"(d) : "l"(a), "l"(b), "l"(c));
    return d;
}

__device__ __forceinline__ void cp_async16(unsigned dst, const void* src, int nbytes) {
    asm volatile("cp.async.cg.shared.global [%0], [%1], 16, %2;"
                 :: "r"(dst), "l"(src), "r"(nbytes));
}
#define CP_COMMIT() asm volatile("cp.async.commit_group;" ::: "memory")
#define CP_WAIT0()  asm volatile("cp.async.wait_group 0;" ::: "memory")

// init sentinels + Sfv
__global__ void init_kernel(int n8, int g8) {
    int i = blockIdx.x * blockDim.x + threadIdx.x;
    if (i < n8) { g_mink[i] = 0x7f800000; g_maxk[i] = 0; }
    if (i < g8) g_Sfv[i] = 0.0f;
}

// no-op spacer so ncu's fixed capture slot (4th launch) lands on edge_kernel
__global__ void spacer_kernel() {}

// ---------------------------------------------------------------------------
// Persistent vertex kernel (exact R9 config: best measured, 179us):
// 512 threads, tile 8Mx4N, tx=lane (unique W LDS.128), m0=warp*8 (broadcast x).
// ---------------------------------------------------------------------------
#define XS_STRIDE 132
#define XS_FLOATS (128 * XS_STRIDE)      // 16896
#define W_OFF     (2 * XS_FLOATS)        // 33792
#define W2_OFF    (W_OFF + 16384)        // 50176
#define B1_OFF    (W2_OFF + 512)
#define B2_OFF    (B1_OFF + 64)
#define SMV_FLOATS (B2_OFF + 8)          // 50760 floats = 203040 B

__device__ __forceinline__ void prefetch_tile(const float* __restrict__ x,
                                              int v0, int N,
                                              unsigned xs_sm, int tid) {
#pragma unroll
    for (int i = 0; i < 8; ++i) {
        int c = tid + i * 512;           // 0..4095 chunk id
        int row = c >> 5, col4 = c & 31;
        unsigned dst = xs_sm + (unsigned)(row * XS_STRIDE + col4 * 4) * 4u;
        const float* src = x + (size_t)(v0 + row) * 128 + col4 * 4;
        int nb = (v0 + row < N) ? 16 : 0;   // zero-fill OOB rows
        cp_async16(dst, src, nb);
    }
}

__global__ __launch_bounds__(512) void vertex_kernel(
    const float* __restrict__ x, const int* __restrict__ batch,
    const float* __restrict__ W1, const float* __restrict__ b1,
    const float* __restrict__ W2, const float* __restrict__ b2,
    const float* __restrict__ We1, int N, int tiles)
{
    extern __shared__ float sm[];
    float* Wsm = sm + W_OFF;
    float* W2s = sm + W2_OFF;
    float* b1s = sm + B1_OFF;
    float* b2s = sm + B2_OFF;

    const int tid = threadIdx.x;
    const unsigned sm_base = (unsigned)__cvta_generic_to_shared(sm);

    for (int i = tid; i < 16384; i += 512) {
        int k = i >> 7, n = i & 127;
        Wsm[i] = (n < 64) ? W1[k * 64 + n] : We1[k * 64 + (n - 64)];
    }
    if (tid < 512) W2s[tid] = W2[tid];
    if (tid < 64) b1s[tid] = b1[tid];
    if (tid < 8)  b2s[tid] = b2[tid];

    const int stride = gridDim.x;
    int pp = 0;
    if ((int)blockIdx.x < tiles)
        prefetch_tile(x, blockIdx.x * 128, N, sm_base, tid);
    CP_COMMIT();
    __syncthreads();

    const int tx = tid & 31;          // lane -> N chunk (32 x 4 cols)
    const int ty = tid >> 5;          // warp -> M chunk (16 x 8 rows)
    const int m0 = ty * 8, n0 = tx * 4;

    for (int t = blockIdx.x; t < tiles; t += stride) {
        CP_WAIT0();
        __syncthreads();

        int tn = t + stride;
        if (tn < tiles)
            prefetch_tile(x, tn * 128, N,
                          sm_base + (unsigned)((pp ^ 1) * XS_FLOATS) * 4u, tid);
        CP_COMMIT();

        float* xs   = sm + pp * XS_FLOATS;
        float* hbuf = xs;
        const int v0 = t * 128;

        unsigned long long acc[8][2];
#pragma unroll
        for (int mi = 0; mi < 8; ++mi) { acc[mi][0] = 0ULL; acc[mi][1] = 0ULL; }

#pragma unroll 2
        for (int k4 = 0; k4 < 128; k4 += 4) {
            float4 xr[8];
#pragma unroll
            for (int mi = 0; mi < 8; ++mi)
                xr[mi] = *reinterpret_cast<const float4*>(
                    xs + (m0 + mi) * XS_STRIDE + k4);   // warp-broadcast
#pragma unroll
            for (int kk = 0; kk < 4; ++kk) {
                float4 wa = *reinterpret_cast<const float4*>(
                    Wsm + ((k4 + kk) << 7) + n0);       // unique per lane
                unsigned long long w0 = pack2(wa.x, wa.y);
                unsigned long long w1p = pack2(wa.z, wa.w);
#pragma unroll
                for (int mi = 0; mi < 8; ++mi) {
                    float xv = (kk == 0) ? xr[mi].x
                             : (kk == 1) ? xr[mi].y
                             : (kk == 2) ? xr[mi].z : xr[mi].w;
                    unsigned long long xx = pack2(xv, xv);
                    acc[mi][0] = ffma2(xx, w0,  acc[mi][0]);
                    acc[mi][1] = ffma2(xx, w1p, acc[mi][1]);
                }
            }
        }
        __syncthreads();

        if (tx < 16) {
#pragma unroll
            for (int mi = 0; mi < 8; ++mi) {
                float* dst = hbuf + (m0 + mi) * XS_STRIDE + n0;
                float l0, h0, l1, h1;
                unpack2(acc[mi][0], l0, h0);
                unpack2(acc[mi][1], l1, h1);
                dst[0] = l0; dst[1] = h0; dst[2] = l1; dst[3] = h1;
            }
        } else {
#pragma unroll
            for (int mi = 0; mi < 8; ++mi) {
                int v = v0 + m0 + mi;
                if (v < N) {
                    float l0, h0, l1, h1;
                    unpack2(acc[mi][0], l0, h0);
                    unpack2(acc[mi][1], l1, h1);
                    *reinterpret_cast<float4*>(g_xW + (size_t)v * 64 + (n0 - 64)) =
                        make_float4(l0, h0, l1, h1);
                }
            }
        }
        __syncthreads();

        if (tid < 128) {
            int v = v0 + tid;
            bool valid = (v < N);
            float a8[8];
#pragma unroll
            for (int f = 0; f < 8; ++f) a8[f] = b2s[f];
            const float* hr = hbuf + tid * XS_STRIDE;
#pragma unroll 4
            for (int k = 0; k < 64; ++k) {
                float hv = fmaxf(hr[k] + b1s[k], 0.0f);
#pragma unroll
                for (int f = 0; f < 8; ++f) a8[f] = fmaf(hv, W2s[k * 8 + f], a8[f]);
            }
#pragma unroll
            for (int f = 0; f < 8; ++f) a8[f] = valid ? sigmoidf_(a8[f]) : 0.0f;

            const unsigned m = 0xffffffffu;
            int lane = tid & 31;
            int gidx = batch[valid ? v : (N - 1)];
            int gl0  = __shfl_sync(m, gidx, 0);
            bool uni = __all_sync(m, gidx == gl0);
            if (uni) {
#pragma unroll
                for (int f = 0; f < 8; ++f) {
                    float s = a8[f];
                    s += __shfl_xor_sync(m, s, 16);
                    s += __shfl_xor_sync(m, s, 8);
                    s += __shfl_xor_sync(m, s, 4);
                    s += __shfl_xor_sync(m, s, 2);
                    s += __shfl_xor_sync(m, s, 1);
                    if (lane == 0) atomicAdd(&g_Sfv[gl0 * 8 + f], s);
                }
            } else if (valid) {
#pragma unroll
                for (int f = 0; f < 8; ++f) atomicAdd(&g_Sfv[gidx * 8 + f], a8[f]);
            }
        }
        pp ^= 1;
    }
}

// ---------------------------------------------------------------------------
// Edge kernel (R13): 16 lanes per edge, 4 channels each.
// We2 staged TRANSPOSED (We2t[f][j], 8x64) -> conflict-free float4 LDS.
// Channel-scattering butterfly reduction: 15 shfl (xor8 full, then keep/send
// halving on channel bits); lane l ends with channel l&7.
// ---------------------------------------------------------------------------
__global__ __launch_bounds__(256) void edge_kernel(
    const float* __restrict__ pos, const int* __restrict__ ei,
    const float* __restrict__ We1, const float* __restrict__ be1,
    const float* __restrict__ We2, const float* __restrict__ be2, int E)
{
    __shared__ __align__(16) float w1l[64];
    __shared__ __align__(16) float be1s[64];
    __shared__ __align__(16) float We2t[512];   // [f][j] transposed
    __shared__ float be2s[8];

    const int tid = threadIdx.x;
    for (int i = tid; i < 64; i += 256) { w1l[i] = We1[8192 + i]; be1s[i] = be1[i]; }
    for (int i = tid; i < 512; i += 256) {
        int f = i >> 6, j = i & 63;
        We2t[i] = We2[j * 8 + f];
    }
    if (tid < 8) be2s[tid] = be2[tid];
    __syncthreads();

    const int l  = tid & 15;               // lane within 16-group
    const int j0 = l * 4;                  // this lane's 4 channels of j
    const int grp = tid >> 4;              // 16 groups per block
    const unsigned fullm = 0xffffffffu;

    for (int e0 = blockIdx.x * 16; e0 < E; e0 += gridDim.x * 16) {
        int e = e0 + grp;
        bool active = (e < E);
        int eidx = active ? e : (E - 1);
        int s = ei[eidx], d = ei[E + eidx];

        float dx = pos[s * 3 + 0] - pos[d * 3 + 0];
        float dy = pos[s * 3 + 1] - pos[d * 3 + 1];
        float dz = pos[s * 3 + 2] - pos[d * 3 + 2];
        float dist = sqrtf(dx * dx + dy * dy + dz * dz);

        float4 aa = *reinterpret_cast<const float4*>(g_xW + (size_t)s * 64 + j0);
        float4 bb = *reinterpret_cast<const float4*>(g_xW + (size_t)d * 64 + j0);
        float4 wl = *reinterpret_cast<const float4*>(w1l + j0);
        float4 bv = *reinterpret_cast<const float4*>(be1s + j0);

        float h0 = fmaxf(fmaf(dist, wl.x, aa.x + bb.x) + bv.x, 0.0f);
        float h1 = fmaxf(fmaf(dist, wl.y, aa.y + bb.y) + bv.y, 0.0f);
        float h2 = fmaxf(fmaf(dist, wl.z, aa.z + bb.z) + bv.z, 0.0f);
        float h3 = fmaxf(fmaf(dist, wl.w, aa.w + bb.w) + bv.w, 0.0f);

        float fe[8];
#pragma unroll
        for (int f = 0; f < 8; ++f) {
            float4 w = *reinterpret_cast<const float4*>(We2t + f * 64 + j0);
            float acc = h0 * w.x;
            acc = fmaf(h1, w.y, acc);
            acc = fmaf(h2, w.z, acc);
            fe[f] = fmaf(h3, w.w, acc);
        }

        // Round A: xor 8 — full 8 channels (both 8-lane halves end identical)
#pragma unroll
        for (int f = 0; f < 8; ++f)
            fe[f] += __shfl_xor_sync(fullm, fe[f], 8);

        // Round B: xor 4 — keep channels with bit2 == (l>>2)&1
        const bool kb2 = (l >> 2) & 1;
        float g4[4];
#pragma unroll
        for (int i = 0; i < 4; ++i) {
            float send = kb2 ? fe[i] : fe[i + 4];
            float recv = __shfl_xor_sync(fullm, send, 4);
            g4[i] = (kb2 ? fe[i + 4] : fe[i]) + recv;
        }
        // Round C: xor 2 — bit1
        const bool kb1 = (l >> 1) & 1;
        float g2[2];
#pragma unroll
        for (int i = 0; i < 2; ++i) {
            float send = kb1 ? g4[i] : g4[i + 2];
            float recv = __shfl_xor_sync(fullm, send, 2);
            g2[i] = (kb1 ? g4[i + 2] : g4[i]) + recv;
        }
        // Round D: xor 1 — bit0
        const bool kb0 = l & 1;
        {
            float send = kb0 ? g2[0] : g2[1];
            float recv = __shfl_xor_sync(fullm, send, 1);
            float tot = (kb0 ? g2[1] : g2[0]) + recv;
            int c = l & 7;                    // channel this lane owns
            int vtx = (l < 8) ? s : d;
            int key = __float_as_int(sigmoidf_(tot + be2s[c]));
            if (active) {
                atomicMin(g_mink + (size_t)vtx * 8 + c, key);
                atomicMax(g_maxk + (size_t)vtx * 8 + c, key);
            }
        }
    }
}

// ---------------------------------------------------------------------------
// Per-graph vertex reduce: fixup sentinels -> 1.0, sum dmin/dmax per graph
// ---------------------------------------------------------------------------
__global__ __launch_bounds__(256) void vreduce_kernel(const int* __restrict__ vs)
{
    __shared__ float rn[8], rx[8];
    const int tid = threadIdx.x, g = blockIdx.x;
    const int v0 = vs[g], v1 = vs[g + 1];
    if (tid < 8) { rn[tid] = 0.0f; rx[tid] = 0.0f; }
    __syncthreads();

    float ln[8], lx[8];
#pragma unroll
    for (int f = 0; f < 8; ++f) { ln[f] = 0.0f; lx[f] = 0.0f; }
    for (int v = v0 + tid; v < v1; v += 256) {
        const int4* mn = reinterpret_cast<const int4*>(g_mink + (size_t)v * 8);
        const int4* mx = reinterpret_cast<const int4*>(g_maxk + (size_t)v * 8);
        int4 a = mn[0], b = mn[1], c = mx[0], d = mx[1];
        ln[0] += (a.x == 0x7f800000) ? 1.0f : __int_as_float(a.x);
        ln[1] += (a.y == 0x7f800000) ? 1.0f : __int_as_float(a.y);
        ln[2] += (a.z == 0x7f800000) ? 1.0f : __int_as_float(a.z);
        ln[3] += (a.w == 0x7f800000) ? 1.0f : __int_as_float(a.w);
        ln[4] += (b.x == 0x7f800000) ? 1.0f : __int_as_float(b.x);
        ln[5] += (b.y == 0x7f800000) ? 1.0f : __int_as_float(b.y);
        ln[6] += (b.z == 0x7f800000) ? 1.0f : __int_as_float(b.z);
        ln[7] += (b.w == 0x7f800000) ? 1.0f : __int_as_float(b.w);
        lx[0] += (c.x == 0) ? 1.0f : __int_as_float(c.x);
        lx[1] += (c.y == 0) ? 1.0f : __int_as_float(c.y);
        lx[2] += (c.z == 0) ? 1.0f : __int_as_float(c.z);
        lx[3] += (c.w == 0) ? 1.0f : __int_as_float(c.w);
        lx[4] += (d.x == 0) ? 1.0f : __int_as_float(d.x);
        lx[5] += (d.y == 0) ? 1.0f : __int_as_float(d.y);
        lx[6] += (d.z == 0) ? 1.0f : __int_as_float(d.z);
        lx[7] += (d.w == 0) ? 1.0f : __int_as_float(d.w);
    }
    const unsigned m = 0xffffffffu;
    int lane = tid & 31;
#pragma unroll
    for (int f = 0; f < 8; ++f) {
        float s = ln[f];
        s += __shfl_xor_sync(m, s, 16); s += __shfl_xor_sync(m, s, 8);
        s += __shfl_xor_sync(m, s, 4);  s += __shfl_xor_sync(m, s, 2);
        s += __shfl_xor_sync(m, s, 1);
        if (lane == 0) atomicAdd(&rn[f], s);
        float t = lx[f];
        t += __shfl_xor_sync(m, t, 16); t += __shfl_xor_sync(m, t, 8);
        t += __shfl_xor_sync(m, t, 4);  t += __shfl_xor_sync(m, t, 2);
        t += __shfl_xor_sync(m, t, 1);
        if (lane == 0) atomicAdd(&rx[f], t);
    }
    __syncthreads();
    if (tid < 8) { g_Smin[g * 8 + tid] = rn[tid]; g_Smax[g * 8 + tid] = rx[tid]; }
}

// h = x0 + x1 (pre-BN)
__global__ void f1_kernel(const float* __restrict__ Wd0, const float* __restrict__ bd0,
                          const float* __restrict__ Wd1, const float* __restrict__ bd1,
                          const int* __restrict__ vs, const int* __restrict__ es)
{
    int g = blockIdx.x, o = threadIdx.x;
    float a = 0.0f;
#pragma unroll
    for (int f = 0; f < 8; ++f) {
        float sf = g_Sfv[g * 8 + f];
        float sx = g_Smax[g * 8 + f];
        float sn = g_Smin[g * 8 + f];
        a = fmaf(sf, Wd0[(4 * f + 1) * 64 + o], a);
        a = fmaf(sx, Wd0[(4 * f + 2) * 64 + o], a);
        a = fmaf(sn, Wd0[(4 * f + 3) * 64 + o], a);
    }
    int nv = vs[g + 1] - vs[g];
    int ne = es[g + 1] - es[g];
    float x0 = a / (float)nv + bd0[o];
    float x1 = (ne - (nv - 1) > 0)
                   ? (Wd1[64 + o] + Wd1[128 + o] + Wd1[192 + o] + bd1[o])
                   : 0.0f;
    g_h[g * 64 + o] = x0 + x1;
}

// BatchNorm stats (two-pass)
__global__ void bn_kernel(int G)
{
    __shared__ float ps[512];
    __shared__ float mu_s[64];
    int t = threadIdx.x, o = t & 63, grp = t >> 6;
    float s = 0.0f;
    for (int r = grp; r < G; r += 8) s += g_h[r * 64 + o];
    ps[t] = s;
    __syncthreads();
    if (t < 64) {
        float S = 0.0f;
        for (int k = 0; k < 8; ++k) S += ps[k * 64 + o];
        mu_s[o] = S / (float)G;
    }
    __syncthreads();
    float mu = mu_s[o];
    s = 0.0f;
    for (int r = grp; r < G; r += 8) { float d = g_h[r * 64 + o] - mu; s = fmaf(d, d, s); }
    ps[t] = s;
    __syncthreads();
    if (t < 64) {
        float S = 0.0f;
        for (int k = 0; k < 8; ++k) S += ps[k * 64 + o];
        g_bn[o] = mu_s[o];
        g_bn[64 + o] = rsqrtf(S / (float)G + 1e-5f);
    }
}

// normalize + out MLP
__global__ __launch_bounds__(1024) void out_kernel(
    const float* __restrict__ gamma, const float* __restrict__ beta,
    const float* __restrict__ Wo1, const float* __restrict__ bo1,
    const float* __restrict__ Wo2, const float* __restrict__ bo2,
    float* __restrict__ out, int G)
{
    __shared__ float hn[16][64];
    __shared__ float t1[16][64];
    int t = threadIdx.x, gl = t >> 6, o = t & 63;
    int g = blockIdx.x * 16 + gl;
    float v = 0.0f;
    if (g < G) v = (g_h[g * 64 + o] - g_bn[o]) * g_bn[64 + o] * gamma[o] + beta[o];
    hn[gl][o] = v;
    __syncthreads();
    float a = bo1[o];
#pragma unroll 8
    for (int k = 0; k < 64; ++k) a = fmaf(hn[gl][k], Wo1[k * 64 + o], a);
    t1[gl][o] = fmaxf(a, 0.0f);
    __syncthreads();
    float b = bo2[o];
#pragma unroll 8
    for (int k = 0; k < 64; ++k) b = fmaf(t1[gl][k], Wo2[k * 64 + o], b);
    if (g < G) out[g * 64 + o] = b;
}

extern "C" void kernel_launch(void* const* d_in, const int* in_sizes, int n_in,
                              void* d_out, int out_size)
{
    const float* x     = (const float*)d_in[0];
    const float* pos   = (const float*)d_in[1];
    const int*   ei    = (const int*)d_in[2];
    const int*   vs    = (const int*)d_in[3];
    const int*   es    = (const int*)d_in[4];
    const int*   batch = (const int*)d_in[5];
    const float* W1  = (const float*)d_in[6];
    const float* b1  = (const float*)d_in[7];
    const float* W2  = (const float*)d_in[8];
    const float* b2  = (const float*)d_in[9];
    const float* We1 = (const float*)d_in[10];
    const float* be1 = (const float*)d_in[11];
    const float* We2 = (const float*)d_in[12];
    const float* be2 = (const float*)d_in[13];
    const float* Wd0 = (const float*)d_in[14];
    const float* bd0 = (const float*)d_in[15];
    const float* Wd1 = (const float*)d_in[16];
    const float* bd1 = (const float*)d_in[17];
    const float* gm  = (const float*)d_in[18];
    const float* bt  = (const float*)d_in[19];
    const float* Wo1 = (const float*)d_in[20];
    const float* bo1 = (const float*)d_in[21];
    const float* Wo2 = (const float*)d_in[22];
    const float* bo2 = (const float*)d_in[23];

    int N = in_sizes[0] / 128;
    int E = in_sizes[2] / 2;
    int G = out_size / 64;
    int tiles = (N + 127) / 128;

    init_kernel<<<(N * 8 + 255) / 256, 256>>>(N * 8, G * 8);   // launch 1
    spacer_kernel<<<1, 32>>>();                                 // launch 2

    size_t smv = (size_t)SMV_FLOATS * sizeof(float);
    cudaFuncSetAttribute(vertex_kernel, cudaFuncAttributeMaxDynamicSharedMemorySize, (int)smv);
    vertex_kernel<<<148, 512, smv>>>(x, batch, W1, b1, W2, b2, We1, N, tiles); // launch 3

    edge_kernel<<<2048, 256>>>(pos, ei, We1, be1, We2, be2, E); // launch 4 (ncu slot)
    vreduce_kernel<<<G, 256>>>(vs);
    f1_kernel<<<G, 64>>>(Wd0, bd0, Wd1, bd1, vs, es);
    bn_kernel<<<1, 512>>>(G);
    out_kernel<<<(G + 15) / 16, 1024>>>(gm, bt, Wo1, bo1, Wo2, bo2, (float*)d_out, G);
}

// round 14
// speedup vs baseline: 1.4211x; 1.0350x over previous
#include <cuda_runtime.h>
#include <cstdint>
#include <cstddef>
#include <math.h>

#define NMAX 204800
#define GMAX 512

// ---- scratch (no allocations allowed) ----
__device__ __align__(16) float g_xW[(size_t)NMAX * 64]; // per-vertex x @ We1[:128] (raw)
__device__ __align__(16) int   g_mink[(size_t)NMAX * 8];
__device__ __align__(16) int   g_maxk[(size_t)NMAX * 8];
__device__ float g_Sfv[GMAX * 8];
__device__ float g_h[GMAX * 64];
__device__ float g_bn[128];

__device__ __forceinline__ float sigmoidf_(float x) {
    return 1.0f / (1.0f + __expf(-x));
}

__device__ __forceinline__ unsigned long long pack2(float lo, float hi) {
    unsigned long long r;
    asm("mov.b64 %0, {%1, %2};" : "=l"(r) : "f"(lo), "f"(hi));
    return r;
}
__device__ __forceinline__ void unpack2(unsigned long long v, float& lo, float& hi) {
    asm("mov.b64 {%0, %1}, %2;" : "=f"(lo), "=f"(hi) : "l"(v));
}
__device__ __forceinline__ unsigned long long ffma2(unsigned long long a,
                                                    unsigned long long b,
                                                    unsigned long long c) {
    unsigned long long d;
    asm("fma.rn.f32x2 %0, %1, %2, %3;" : "=l"(d) : "l"(a), "l"(b), "l"(c));
    return d;
}

__device__ __forceinline__ void cp_async16(unsigned dst, const void* src, int nbytes) {
    asm volatile("cp.async.cg.shared.global [%0], [%1], 16, %2;"
                 :: "r"(dst), "l"(src), "r"(nbytes));
}
#define CP_COMMIT() asm volatile("cp.async.commit_group;" ::: "memory")
#define CP_WAIT0()  asm volatile("cp.async.wait_group 0;" ::: "memory")

// init sentinels + Sfv
__global__ void init_kernel(int n8, int g8) {
    int i = blockIdx.x * blockDim.x + threadIdx.x;
    if (i < n8) { g_mink[i] = 0x7f800000; g_maxk[i] = 0; }
    if (i < g8) g_Sfv[i] = 0.0f;
}

// no-op spacer so ncu's fixed capture slot (4th launch) lands on edge_kernel
__global__ void spacer_kernel() {}

// ---------------------------------------------------------------------------
// Persistent vertex kernel (exact R9 config: best measured, 179us).
// ---------------------------------------------------------------------------
#define XS_STRIDE 132
#define XS_FLOATS (128 * XS_STRIDE)      // 16896
#define W_OFF     (2 * XS_FLOATS)        // 33792
#define W2_OFF    (W_OFF + 16384)        // 50176
#define B1_OFF    (W2_OFF + 512)
#define B2_OFF    (B1_OFF + 64)
#define SMV_FLOATS (B2_OFF + 8)          // 50760 floats = 203040 B

__device__ __forceinline__ void prefetch_tile(const float* __restrict__ x,
                                              int v0, int N,
                                              unsigned xs_sm, int tid) {
#pragma unroll
    for (int i = 0; i < 8; ++i) {
        int c = tid + i * 512;
        int row = c >> 5, col4 = c & 31;
        unsigned dst = xs_sm + (unsigned)(row * XS_STRIDE + col4 * 4) * 4u;
        const float* src = x + (size_t)(v0 + row) * 128 + col4 * 4;
        int nb = (v0 + row < N) ? 16 : 0;
        cp_async16(dst, src, nb);
    }
}

__global__ __launch_bounds__(512) void vertex_kernel(
    const float* __restrict__ x, const int* __restrict__ batch,
    const float* __restrict__ W1, const float* __restrict__ b1,
    const float* __restrict__ W2, const float* __restrict__ b2,
    const float* __restrict__ We1, int N, int tiles)
{
    extern __shared__ float sm[];
    float* Wsm = sm + W_OFF;
    float* W2s = sm + W2_OFF;
    float* b1s = sm + B1_OFF;
    float* b2s = sm + B2_OFF;

    const int tid = threadIdx.x;
    const unsigned sm_base = (unsigned)__cvta_generic_to_shared(sm);

    for (int i = tid; i < 16384; i += 512) {
        int k = i >> 7, n = i & 127;
        Wsm[i] = (n < 64) ? W1[k * 64 + n] : We1[k * 64 + (n - 64)];
    }
    if (tid < 512) W2s[tid] = W2[tid];
    if (tid < 64) b1s[tid] = b1[tid];
    if (tid < 8)  b2s[tid] = b2[tid];

    const int stride = gridDim.x;
    int pp = 0;
    if ((int)blockIdx.x < tiles)
        prefetch_tile(x, blockIdx.x * 128, N, sm_base, tid);
    CP_COMMIT();
    __syncthreads();

    const int tx = tid & 31;
    const int ty = tid >> 5;
    const int m0 = ty * 8, n0 = tx * 4;

    for (int t = blockIdx.x; t < tiles; t += stride) {
        CP_WAIT0();
        __syncthreads();

        int tn = t + stride;
        if (tn < tiles)
            prefetch_tile(x, tn * 128, N,
                          sm_base + (unsigned)((pp ^ 1) * XS_FLOATS) * 4u, tid);
        CP_COMMIT();

        float* xs   = sm + pp * XS_FLOATS;
        float* hbuf = xs;
        const int v0 = t * 128;

        unsigned long long acc[8][2];
#pragma unroll
        for (int mi = 0; mi < 8; ++mi) { acc[mi][0] = 0ULL; acc[mi][1] = 0ULL; }

#pragma unroll 2
        for (int k4 = 0; k4 < 128; k4 += 4) {
            float4 xr[8];
#pragma unroll
            for (int mi = 0; mi < 8; ++mi)
                xr[mi] = *reinterpret_cast<const float4*>(
                    xs + (m0 + mi) * XS_STRIDE + k4);
#pragma unroll
            for (int kk = 0; kk < 4; ++kk) {
                float4 wa = *reinterpret_cast<const float4*>(
                    Wsm + ((k4 + kk) << 7) + n0);
                unsigned long long w0 = pack2(wa.x, wa.y);
                unsigned long long w1p = pack2(wa.z, wa.w);
#pragma unroll
                for (int mi = 0; mi < 8; ++mi) {
                    float xv = (kk == 0) ? xr[mi].x
                             : (kk == 1) ? xr[mi].y
                             : (kk == 2) ? xr[mi].z : xr[mi].w;
                    unsigned long long xx = pack2(xv, xv);
                    acc[mi][0] = ffma2(xx, w0,  acc[mi][0]);
                    acc[mi][1] = ffma2(xx, w1p, acc[mi][1]);
                }
            }
        }
        __syncthreads();

        if (tx < 16) {
#pragma unroll
            for (int mi = 0; mi < 8; ++mi) {
                float* dst = hbuf + (m0 + mi) * XS_STRIDE + n0;
                float l0, h0, l1, h1;
                unpack2(acc[mi][0], l0, h0);
                unpack2(acc[mi][1], l1, h1);
                dst[0] = l0; dst[1] = h0; dst[2] = l1; dst[3] = h1;
            }
        } else {
#pragma unroll
            for (int mi = 0; mi < 8; ++mi) {
                int v = v0 + m0 + mi;
                if (v < N) {
                    float l0, h0, l1, h1;
                    unpack2(acc[mi][0], l0, h0);
                    unpack2(acc[mi][1], l1, h1);
                    *reinterpret_cast<float4*>(g_xW + (size_t)v * 64 + (n0 - 64)) =
                        make_float4(l0, h0, l1, h1);
                }
            }
        }
        __syncthreads();

        if (tid < 128) {
            int v = v0 + tid;
            bool valid = (v < N);
            float a8[8];
#pragma unroll
            for (int f = 0; f < 8; ++f) a8[f] = b2s[f];
            const float* hr = hbuf + tid * XS_STRIDE;
#pragma unroll 4
            for (int k = 0; k < 64; ++k) {
                float hv = fmaxf(hr[k] + b1s[k], 0.0f);
#pragma unroll
                for (int f = 0; f < 8; ++f) a8[f] = fmaf(hv, W2s[k * 8 + f], a8[f]);
            }
#pragma unroll
            for (int f = 0; f < 8; ++f) a8[f] = valid ? sigmoidf_(a8[f]) : 0.0f;

            const unsigned m = 0xffffffffu;
            int lane = tid & 31;
            int gidx = batch[valid ? v : (N - 1)];
            int gl0  = __shfl_sync(m, gidx, 0);
            bool uni = __all_sync(m, gidx == gl0);
            if (uni) {
#pragma unroll
                for (int f = 0; f < 8; ++f) {
                    float s = a8[f];
                    s += __shfl_xor_sync(m, s, 16);
                    s += __shfl_xor_sync(m, s, 8);
                    s += __shfl_xor_sync(m, s, 4);
                    s += __shfl_xor_sync(m, s, 2);
                    s += __shfl_xor_sync(m, s, 1);
                    if (lane == 0) atomicAdd(&g_Sfv[gl0 * 8 + f], s);
                }
            } else if (valid) {
#pragma unroll
                for (int f = 0; f < 8; ++f) atomicAdd(&g_Sfv[gidx * 8 + f], a8[f]);
            }
        }
        pp ^= 1;
    }
}

// ---------------------------------------------------------------------------
// Edge kernel (R14): 16 lanes per edge, 2 EDGES per group per iteration to
// double memory-level parallelism. Transposed We2 (conflict-free LDS),
// channel-scattering butterfly (15 shfl per edge).
// ---------------------------------------------------------------------------
struct EdgeVals { int s, d; float dist; bool active; };

__device__ __forceinline__ void edge_reduce_and_store(
    float fe[8], int l, int s, int d, bool active, const float* be2s)
{
    const unsigned fullm = 0xffffffffu;
#pragma unroll
    for (int f = 0; f < 8; ++f)
        fe[f] += __shfl_xor_sync(fullm, fe[f], 8);
    const bool kb2 = (l >> 2) & 1;
    float g4[4];
#pragma unroll
    for (int i = 0; i < 4; ++i) {
        float send = kb2 ? fe[i] : fe[i + 4];
        float recv = __shfl_xor_sync(fullm, send, 4);
        g4[i] = (kb2 ? fe[i + 4] : fe[i]) + recv;
    }
    const bool kb1 = (l >> 1) & 1;
    float g2[2];
#pragma unroll
    for (int i = 0; i < 2; ++i) {
        float send = kb1 ? g4[i] : g4[i + 2];
        float recv = __shfl_xor_sync(fullm, send, 2);
        g2[i] = (kb1 ? g4[i + 2] : g4[i]) + recv;
    }
    const bool kb0 = l & 1;
    float send = kb0 ? g2[0] : g2[1];
    float recv = __shfl_xor_sync(fullm, send, 1);
    float tot = (kb0 ? g2[1] : g2[0]) + recv;
    int c = l & 7;
    int vtx = (l < 8) ? s : d;
    int key = __float_as_int(sigmoidf_(tot + be2s[c]));
    if (active) {
        atomicMin(g_mink + (size_t)vtx * 8 + c, key);
        atomicMax(g_maxk + (size_t)vtx * 8 + c, key);
    }
}

__global__ __launch_bounds__(256) void edge_kernel(
    const float* __restrict__ pos, const int* __restrict__ ei,
    const float* __restrict__ We1, const float* __restrict__ be1,
    const float* __restrict__ We2, const float* __restrict__ be2, int E)
{
    __shared__ __align__(16) float w1l[64];
    __shared__ __align__(16) float be1s[64];
    __shared__ __align__(16) float We2t[512];   // [f][j] transposed
    __shared__ float be2s[8];

    const int tid = threadIdx.x;
    for (int i = tid; i < 64; i += 256) { w1l[i] = We1[8192 + i]; be1s[i] = be1[i]; }
    for (int i = tid; i < 512; i += 256) {
        int f = i >> 6, j = i & 63;
        We2t[i] = We2[j * 8 + f];
    }
    if (tid < 8) be2s[tid] = be2[tid];
    __syncthreads();

    const int l  = tid & 15;
    const int j0 = l * 4;
    const int grp = tid >> 4;

    const float4 wl = *reinterpret_cast<const float4*>(w1l + j0);
    const float4 bv = *reinterpret_cast<const float4*>(be1s + j0);

    for (int e0 = blockIdx.x * 32; e0 < E; e0 += gridDim.x * 32) {
        int ea = e0 + grp;
        int eb = e0 + 16 + grp;
        bool actA = (ea < E), actB = (eb < E);
        int ia = actA ? ea : (E - 1);
        int ib = actB ? eb : (E - 1);

        // --- issue all index + pos loads (both edges) ---
        int sA = ei[ia], dA = ei[E + ia];
        int sB = ei[ib], dB = ei[E + ib];
        float ax = pos[sA * 3 + 0] - pos[dA * 3 + 0];
        float ay = pos[sA * 3 + 1] - pos[dA * 3 + 1];
        float az = pos[sA * 3 + 2] - pos[dA * 3 + 2];
        float bx = pos[sB * 3 + 0] - pos[dB * 3 + 0];
        float by = pos[sB * 3 + 1] - pos[dB * 3 + 1];
        float bz = pos[sB * 3 + 2] - pos[dB * 3 + 2];

        // --- issue all 4 gathers before consuming any ---
        float4 aA = *reinterpret_cast<const float4*>(g_xW + (size_t)sA * 64 + j0);
        float4 bA = *reinterpret_cast<const float4*>(g_xW + (size_t)dA * 64 + j0);
        float4 aB = *reinterpret_cast<const float4*>(g_xW + (size_t)sB * 64 + j0);
        float4 bB = *reinterpret_cast<const float4*>(g_xW + (size_t)dB * 64 + j0);

        float distA = sqrtf(ax * ax + ay * ay + az * az);
        float distB = sqrtf(bx * bx + by * by + bz * bz);

        // --- edge A ---
        float feA[8];
        {
            float h0 = fmaxf(fmaf(distA, wl.x, aA.x + bA.x) + bv.x, 0.0f);
            float h1 = fmaxf(fmaf(distA, wl.y, aA.y + bA.y) + bv.y, 0.0f);
            float h2 = fmaxf(fmaf(distA, wl.z, aA.z + bA.z) + bv.z, 0.0f);
            float h3 = fmaxf(fmaf(distA, wl.w, aA.w + bA.w) + bv.w, 0.0f);
#pragma unroll
            for (int f = 0; f < 8; ++f) {
                float4 w = *reinterpret_cast<const float4*>(We2t + f * 64 + j0);
                float acc = h0 * w.x;
                acc = fmaf(h1, w.y, acc);
                acc = fmaf(h2, w.z, acc);
                feA[f] = fmaf(h3, w.w, acc);
            }
        }
        // --- edge B ---
        float feB[8];
        {
            float h0 = fmaxf(fmaf(distB, wl.x, aB.x + bB.x) + bv.x, 0.0f);
            float h1 = fmaxf(fmaf(distB, wl.y, aB.y + bB.y) + bv.y, 0.0f);
            float h2 = fmaxf(fmaf(distB, wl.z, aB.z + bB.z) + bv.z, 0.0f);
            float h3 = fmaxf(fmaf(distB, wl.w, aB.w + bB.w) + bv.w, 0.0f);
#pragma unroll
            for (int f = 0; f < 8; ++f) {
                float4 w = *reinterpret_cast<const float4*>(We2t + f * 64 + j0);
                float acc = h0 * w.x;
                acc = fmaf(h1, w.y, acc);
                acc = fmaf(h2, w.z, acc);
                feB[f] = fmaf(h3, w.w, acc);
            }
        }

        edge_reduce_and_store(feA, l, sA, dA, actA, be2s);
        edge_reduce_and_store(feB, l, sB, dB, actB, be2s);
    }
}

// ---------------------------------------------------------------------------
// Fused per-graph vertex reduce + f1: sentinel fixup, per-graph sums, then
// h = x0 + x1 directly (no f1 kernel, no Smin/Smax global round-trip).
// ---------------------------------------------------------------------------
__global__ __launch_bounds__(256) void vreduce_f1_kernel(
    const int* __restrict__ vs, const int* __restrict__ es,
    const float* __restrict__ Wd0, const float* __restrict__ bd0,
    const float* __restrict__ Wd1, const float* __restrict__ bd1)
{
    __shared__ float rn[8], rx[8];
    const int tid = threadIdx.x, g = blockIdx.x;
    const int v0 = vs[g], v1 = vs[g + 1];
    if (tid < 8) { rn[tid] = 0.0f; rx[tid] = 0.0f; }
    __syncthreads();

    float ln[8], lx[8];
#pragma unroll
    for (int f = 0; f < 8; ++f) { ln[f] = 0.0f; lx[f] = 0.0f; }
    for (int v = v0 + tid; v < v1; v += 256) {
        const int4* mn = reinterpret_cast<const int4*>(g_mink + (size_t)v * 8);
        const int4* mx = reinterpret_cast<const int4*>(g_maxk + (size_t)v * 8);
        int4 a = mn[0], b = mn[1], c = mx[0], d = mx[1];
        ln[0] += (a.x == 0x7f800000) ? 1.0f : __int_as_float(a.x);
        ln[1] += (a.y == 0x7f800000) ? 1.0f : __int_as_float(a.y);
        ln[2] += (a.z == 0x7f800000) ? 1.0f : __int_as_float(a.z);
        ln[3] += (a.w == 0x7f800000) ? 1.0f : __int_as_float(a.w);
        ln[4] += (b.x == 0x7f800000) ? 1.0f : __int_as_float(b.x);
        ln[5] += (b.y == 0x7f800000) ? 1.0f : __int_as_float(b.y);
        ln[6] += (b.z == 0x7f800000) ? 1.0f : __int_as_float(b.z);
        ln[7] += (b.w == 0x7f800000) ? 1.0f : __int_as_float(b.w);
        lx[0] += (c.x == 0) ? 1.0f : __int_as_float(c.x);
        lx[1] += (c.y == 0) ? 1.0f : __int_as_float(c.y);
        lx[2] += (c.z == 0) ? 1.0f : __int_as_float(c.z);
        lx[3] += (c.w == 0) ? 1.0f : __int_as_float(c.w);
        lx[4] += (d.x == 0) ? 1.0f : __int_as_float(d.x);
        lx[5] += (d.y == 0) ? 1.0f : __int_as_float(d.y);
        lx[6] += (d.z == 0) ? 1.0f : __int_as_float(d.z);
        lx[7] += (d.w == 0) ? 1.0f : __int_as_float(d.w);
    }
    const unsigned m = 0xffffffffu;
    int lane = tid & 31;
#pragma unroll
    for (int f = 0; f < 8; ++f) {
        float s = ln[f];
        s += __shfl_xor_sync(m, s, 16); s += __shfl_xor_sync(m, s, 8);
        s += __shfl_xor_sync(m, s, 4);  s += __shfl_xor_sync(m, s, 2);
        s += __shfl_xor_sync(m, s, 1);
        if (lane == 0) atomicAdd(&rn[f], s);
        float t = lx[f];
        t += __shfl_xor_sync(m, t, 16); t += __shfl_xor_sync(m, t, 8);
        t += __shfl_xor_sync(m, t, 4);  t += __shfl_xor_sync(m, t, 2);
        t += __shfl_xor_sync(m, t, 1);
        if (lane == 0) atomicAdd(&rx[f], t);
    }
    __syncthreads();

    // fused f1: h = x0 + x1 for this graph (threads 0..63)
    if (tid < 64) {
        int o = tid;
        float a = 0.0f;
#pragma unroll
        for (int f = 0; f < 8; ++f) {
            a = fmaf(g_Sfv[g * 8 + f], Wd0[(4 * f + 1) * 64 + o], a);
            a = fmaf(rx[f],            Wd0[(4 * f + 2) * 64 + o], a);
            a = fmaf(rn[f],            Wd0[(4 * f + 3) * 64 + o], a);
        }
        int nv = v1 - v0;
        int ne = es[g + 1] - es[g];
        float x0 = a / (float)nv + bd0[o];
        float x1 = (ne - (nv - 1) > 0)
                       ? (Wd1[64 + o] + Wd1[128 + o] + Wd1[192 + o] + bd1[o])
                       : 0.0f;
        g_h[g * 64 + o] = x0 + x1;
    }
}

// BatchNorm stats (two-pass)
__global__ void bn_kernel(int G)
{
    __shared__ float ps[512];
    __shared__ float mu_s[64];
    int t = threadIdx.x, o = t & 63, grp = t >> 6;
    float s = 0.0f;
    for (int r = grp; r < G; r += 8) s += g_h[r * 64 + o];
    ps[t] = s;
    __syncthreads();
    if (t < 64) {
        float S = 0.0f;
        for (int k = 0; k < 8; ++k) S += ps[k * 64 + o];
        mu_s[o] = S / (float)G;
    }
    __syncthreads();
    float mu = mu_s[o];
    s = 0.0f;
    for (int r = grp; r < G; r += 8) { float d = g_h[r * 64 + o] - mu; s = fmaf(d, d, s); }
    ps[t] = s;
    __syncthreads();
    if (t < 64) {
        float S = 0.0f;
        for (int k = 0; k < 8; ++k) S += ps[k * 64 + o];
        g_bn[o] = mu_s[o];
        g_bn[64 + o] = rsqrtf(S / (float)G + 1e-5f);
    }
}

// normalize + out MLP
__global__ __launch_bounds__(1024) void out_kernel(
    const float* __restrict__ gamma, const float* __restrict__ beta,
    const float* __restrict__ Wo1, const float* __restrict__ bo1,
    const float* __restrict__ Wo2, const float* __restrict__ bo2,
    float* __restrict__ out, int G)
{
    __shared__ float hn[16][64];
    __shared__ float t1[16][64];
    int t = threadIdx.x, gl = t >> 6, o = t & 63;
    int g = blockIdx.x * 16 + gl;
    float v = 0.0f;
    if (g < G) v = (g_h[g * 64 + o] - g_bn[o]) * g_bn[64 + o] * gamma[o] + beta[o];
    hn[gl][o] = v;
    __syncthreads();
    float a = bo1[o];
#pragma unroll 8
    for (int k = 0; k < 64; ++k) a = fmaf(hn[gl][k], Wo1[k * 64 + o], a);
    t1[gl][o] = fmaxf(a, 0.0f);
    __syncthreads();
    float b = bo2[o];
#pragma unroll 8
    for (int k = 0; k < 64; ++k) b = fmaf(t1[gl][k], Wo2[k * 64 + o], b);
    if (g < G) out[g * 64 + o] = b;
}

extern "C" void kernel_launch(void* const* d_in, const int* in_sizes, int n_in,
                              void* d_out, int out_size)
{
    const float* x     = (const float*)d_in[0];
    const float* pos   = (const float*)d_in[1];
    const int*   ei    = (const int*)d_in[2];
    const int*   vs    = (const int*)d_in[3];
    const int*   es    = (const int*)d_in[4];
    const int*   batch = (const int*)d_in[5];
    const float* W1  = (const float*)d_in[6];
    const float* b1  = (const float*)d_in[7];
    const float* W2  = (const float*)d_in[8];
    const float* b2  = (const float*)d_in[9];
    const float* We1 = (const float*)d_in[10];
    const float* be1 = (const float*)d_in[11];
    const float* We2 = (const float*)d_in[12];
    const float* be2 = (const float*)d_in[13];
    const float* Wd0 = (const float*)d_in[14];
    const float* bd0 = (const float*)d_in[15];
    const float* Wd1 = (const float*)d_in[16];
    const float* bd1 = (const float*)d_in[17];
    const float* gm  = (const float*)d_in[18];
    const float* bt  = (const float*)d_in[19];
    const float* Wo1 = (const float*)d_in[20];
    const float* bo1 = (const float*)d_in[21];
    const float* Wo2 = (const float*)d_in[22];
    const float* bo2 = (const float*)d_in[23];

    int N = in_sizes[0] / 128;
    int E = in_sizes[2] / 2;
    int G = out_size / 64;
    int tiles = (N + 127) / 128;

    init_kernel<<<(N * 8 + 255) / 256, 256>>>(N * 8, G * 8);   // launch 1
    spacer_kernel<<<1, 32>>>();                                 // launch 2

    size_t smv = (size_t)SMV_FLOATS * sizeof(float);
    cudaFuncSetAttribute(vertex_kernel, cudaFuncAttributeMaxDynamicSharedMemorySize, (int)smv);
    vertex_kernel<<<148, 512, smv>>>(x, batch, W1, b1, W2, b2, We1, N, tiles); // launch 3

    edge_kernel<<<2048, 256>>>(pos, ei, We1, be1, We2, be2, E); // launch 4 (ncu slot)
    vreduce_f1_kernel<<<G, 256>>>(vs, es, Wd0, bd0, Wd1, bd1);
    bn_kernel<<<1, 512>>>(G);
    out_kernel<<<(G + 15) / 16, 1024>>>(gm, bt, Wo1, bo1, Wo2, bo2, (float*)d_out, G);
}

// round 15
// speedup vs baseline: 1.4411x; 1.0141x over previous
#include <cuda_runtime.h>
#include <cstdint>
#include <cstddef>
#include <math.h>

#define NMAX 204800
#define GMAX 512

// ---- scratch (no allocations allowed) ----
__device__ __align__(16) float g_xW[(size_t)NMAX * 64]; // per-vertex x @ We1[:128] (raw)
__device__ __align__(16) int   g_mink[(size_t)NMAX * 8];
__device__ __align__(16) int   g_maxk[(size_t)NMAX * 8];
__device__ float g_Sfv[GMAX * 8];
__device__ float g_h[GMAX * 64];
__device__ float g_bn[128];

__device__ __forceinline__ float sigmoidf_(float x) {
    return 1.0f / (1.0f + __expf(-x));
}

__device__ __forceinline__ unsigned long long pack2(float lo, float hi) {
    unsigned long long r;
    asm("mov.b64 %0, {%1, %2};" : "=l"(r) : "f"(lo), "f"(hi));
    return r;
}
__device__ __forceinline__ void unpack2(unsigned long long v, float& lo, float& hi) {
    asm("mov.b64 {%0, %1}, %2;" : "=f"(lo), "=f"(hi) : "l"(v));
}
__device__ __forceinline__ unsigned long long ffma2(unsigned long long a,
                                                    unsigned long long b,
                                                    unsigned long long c) {
    unsigned long long d;
    asm("fma.rn.f32x2 %0, %1, %2, %3;" : "=l"(d) : "l"(a), "l"(b), "l"(c));
    return d;
}

__device__ __forceinline__ void cp_async16(unsigned dst, const void* src, int nbytes) {
    asm volatile("cp.async.cg.shared.global [%0], [%1], 16, %2;"
                 :: "r"(dst), "l"(src), "r"(nbytes));
}
#define CP_COMMIT() asm volatile("cp.async.commit_group;" ::: "memory")
#define CP_WAIT0()  asm volatile("cp.async.wait_group 0;" ::: "memory")

// init sentinels + Sfv
__global__ void init_kernel(int n8, int g8) {
    int i = blockIdx.x * blockDim.x + threadIdx.x;
    if (i < n8) { g_mink[i] = 0x7f800000; g_maxk[i] = 0; }
    if (i < g8) g_Sfv[i] = 0.0f;
}

// no-op spacer so ncu's fixed capture slot (4th launch) lands on edge_kernel
__global__ void spacer_kernel() {}

// ---------------------------------------------------------------------------
// Persistent vertex kernel (R9 config + vectorized fv epilogue reads).
// ---------------------------------------------------------------------------
#define XS_STRIDE 132
#define XS_FLOATS (128 * XS_STRIDE)      // 16896
#define W_OFF     (2 * XS_FLOATS)        // 33792
#define W2_OFF    (W_OFF + 16384)        // 50176
#define B1_OFF    (W2_OFF + 512)
#define B2_OFF    (B1_OFF + 64)
#define SMV_FLOATS (B2_OFF + 8)          // 50760 floats = 203040 B

__device__ __forceinline__ void prefetch_tile(const float* __restrict__ x,
                                              int v0, int N,
                                              unsigned xs_sm, int tid) {
#pragma unroll
    for (int i = 0; i < 8; ++i) {
        int c = tid + i * 512;
        int row = c >> 5, col4 = c & 31;
        unsigned dst = xs_sm + (unsigned)(row * XS_STRIDE + col4 * 4) * 4u;
        const float* src = x + (size_t)(v0 + row) * 128 + col4 * 4;
        int nb = (v0 + row < N) ? 16 : 0;
        cp_async16(dst, src, nb);
    }
}

__global__ __launch_bounds__(512) void vertex_kernel(
    const float* __restrict__ x, const int* __restrict__ batch,
    const float* __restrict__ W1, const float* __restrict__ b1,
    const float* __restrict__ W2, const float* __restrict__ b2,
    const float* __restrict__ We1, int N, int tiles)
{
    extern __shared__ float sm[];
    float* Wsm = sm + W_OFF;
    float* W2s = sm + W2_OFF;
    float* b1s = sm + B1_OFF;
    float* b2s = sm + B2_OFF;

    const int tid = threadIdx.x;
    const unsigned sm_base = (unsigned)__cvta_generic_to_shared(sm);

    for (int i = tid; i < 16384; i += 512) {
        int k = i >> 7, n = i & 127;
        Wsm[i] = (n < 64) ? W1[k * 64 + n] : We1[k * 64 + (n - 64)];
    }
    if (tid < 512) W2s[tid] = W2[tid];
    if (tid < 64) b1s[tid] = b1[tid];
    if (tid < 8)  b2s[tid] = b2[tid];

    const int stride = gridDim.x;
    int pp = 0;
    if ((int)blockIdx.x < tiles)
        prefetch_tile(x, blockIdx.x * 128, N, sm_base, tid);
    CP_COMMIT();
    __syncthreads();

    const int tx = tid & 31;
    const int ty = tid >> 5;
    const int m0 = ty * 8, n0 = tx * 4;

    for (int t = blockIdx.x; t < tiles; t += stride) {
        CP_WAIT0();
        __syncthreads();

        int tn = t + stride;
        if (tn < tiles)
            prefetch_tile(x, tn * 128, N,
                          sm_base + (unsigned)((pp ^ 1) * XS_FLOATS) * 4u, tid);
        CP_COMMIT();

        float* xs   = sm + pp * XS_FLOATS;
        float* hbuf = xs;
        const int v0 = t * 128;

        unsigned long long acc[8][2];
#pragma unroll
        for (int mi = 0; mi < 8; ++mi) { acc[mi][0] = 0ULL; acc[mi][1] = 0ULL; }

#pragma unroll 2
        for (int k4 = 0; k4 < 128; k4 += 4) {
            float4 xr[8];
#pragma unroll
            for (int mi = 0; mi < 8; ++mi)
                xr[mi] = *reinterpret_cast<const float4*>(
                    xs + (m0 + mi) * XS_STRIDE + k4);
#pragma unroll
            for (int kk = 0; kk < 4; ++kk) {
                float4 wa = *reinterpret_cast<const float4*>(
                    Wsm + ((k4 + kk) << 7) + n0);
                unsigned long long w0 = pack2(wa.x, wa.y);
                unsigned long long w1p = pack2(wa.z, wa.w);
#pragma unroll
                for (int mi = 0; mi < 8; ++mi) {
                    float xv = (kk == 0) ? xr[mi].x
                             : (kk == 1) ? xr[mi].y
                             : (kk == 2) ? xr[mi].z : xr[mi].w;
                    unsigned long long xx = pack2(xv, xv);
                    acc[mi][0] = ffma2(xx, w0,  acc[mi][0]);
                    acc[mi][1] = ffma2(xx, w1p, acc[mi][1]);
                }
            }
        }
        __syncthreads();

        if (tx < 16) {
#pragma unroll
            for (int mi = 0; mi < 8; ++mi) {
                float* dst = hbuf + (m0 + mi) * XS_STRIDE + n0;
                float l0, h0, l1, h1;
                unpack2(acc[mi][0], l0, h0);
                unpack2(acc[mi][1], l1, h1);
                dst[0] = l0; dst[1] = h0; dst[2] = l1; dst[3] = h1;
            }
        } else {
#pragma unroll
            for (int mi = 0; mi < 8; ++mi) {
                int v = v0 + m0 + mi;
                if (v < N) {
                    float l0, h0, l1, h1;
                    unpack2(acc[mi][0], l0, h0);
                    unpack2(acc[mi][1], l1, h1);
                    *reinterpret_cast<float4*>(g_xW + (size_t)v * 64 + (n0 - 64)) =
                        make_float4(l0, h0, l1, h1);
                }
            }
        }
        __syncthreads();

        // fv epilogue: one vertex per thread (tid<128), float4 hbuf reads
        if (tid < 128) {
            int v = v0 + tid;
            bool valid = (v < N);
            float a8[8];
#pragma unroll
            for (int f = 0; f < 8; ++f) a8[f] = b2s[f];
            const float4* hr4 = reinterpret_cast<const float4*>(hbuf + tid * XS_STRIDE);
#pragma unroll 4
            for (int kq = 0; kq < 16; ++kq) {
                float4 hv4 = hr4[kq];
                int k = kq * 4;
                float hv0 = fmaxf(hv4.x + b1s[k + 0], 0.0f);
                float hv1 = fmaxf(hv4.y + b1s[k + 1], 0.0f);
                float hv2 = fmaxf(hv4.z + b1s[k + 2], 0.0f);
                float hv3 = fmaxf(hv4.w + b1s[k + 3], 0.0f);
                const float* w0 = W2s + k * 8;
#pragma unroll
                for (int f = 0; f < 8; ++f) {
                    float acc = fmaf(hv0, w0[f], a8[f]);
                    acc = fmaf(hv1, w0[8 + f], acc);
                    acc = fmaf(hv2, w0[16 + f], acc);
                    a8[f] = fmaf(hv3, w0[24 + f], acc);
                }
            }
#pragma unroll
            for (int f = 0; f < 8; ++f) a8[f] = valid ? sigmoidf_(a8[f]) : 0.0f;

            const unsigned m = 0xffffffffu;
            int lane = tid & 31;
            int gidx = batch[valid ? v : (N - 1)];
            int gl0  = __shfl_sync(m, gidx, 0);
            bool uni = __all_sync(m, gidx == gl0);
            if (uni) {
#pragma unroll
                for (int f = 0; f < 8; ++f) {
                    float s = a8[f];
                    s += __shfl_xor_sync(m, s, 16);
                    s += __shfl_xor_sync(m, s, 8);
                    s += __shfl_xor_sync(m, s, 4);
                    s += __shfl_xor_sync(m, s, 2);
                    s += __shfl_xor_sync(m, s, 1);
                    if (lane == 0) atomicAdd(&g_Sfv[gl0 * 8 + f], s);
                }
            } else if (valid) {
#pragma unroll
                for (int f = 0; f < 8; ++f) atomicAdd(&g_Sfv[gidx * 8 + f], a8[f]);
            }
        }
        pp ^= 1;
    }
}

// ---------------------------------------------------------------------------
// Edge kernel (R15): 16 lanes per edge, 4 EDGES per group per iteration
// (deep MLP), __launch_bounds__(256,2) for register headroom (<=128, no
// spills). Transposed We2, channel-scattering butterfly (15 shfl/edge).
// ---------------------------------------------------------------------------
__device__ __forceinline__ void edge_reduce_and_store(
    float fe[8], int l, int s, int d, bool active, const float* be2s)
{
    const unsigned fullm = 0xffffffffu;
#pragma unroll
    for (int f = 0; f < 8; ++f)
        fe[f] += __shfl_xor_sync(fullm, fe[f], 8);
    const bool kb2 = (l >> 2) & 1;
    float g4[4];
#pragma unroll
    for (int i = 0; i < 4; ++i) {
        float send = kb2 ? fe[i] : fe[i + 4];
        float recv = __shfl_xor_sync(fullm, send, 4);
        g4[i] = (kb2 ? fe[i + 4] : fe[i]) + recv;
    }
    const bool kb1 = (l >> 1) & 1;
    float g2[2];
#pragma unroll
    for (int i = 0; i < 2; ++i) {
        float send = kb1 ? g4[i] : g4[i + 2];
        float recv = __shfl_xor_sync(fullm, send, 2);
        g2[i] = (kb1 ? g4[i + 2] : g4[i]) + recv;
    }
    const bool kb0 = l & 1;
    float send = kb0 ? g2[0] : g2[1];
    float recv = __shfl_xor_sync(fullm, send, 1);
    float tot = (kb0 ? g2[1] : g2[0]) + recv;
    int c = l & 7;
    int vtx = (l < 8) ? s : d;
    int key = __float_as_int(sigmoidf_(tot + be2s[c]));
    if (active) {
        atomicMin(g_mink + (size_t)vtx * 8 + c, key);
        atomicMax(g_maxk + (size_t)vtx * 8 + c, key);
    }
}

__global__ __launch_bounds__(256, 2) void edge_kernel(
    const float* __restrict__ pos, const int* __restrict__ ei,
    const float* __restrict__ We1, const float* __restrict__ be1,
    const float* __restrict__ We2, const float* __restrict__ be2, int E)
{
    __shared__ __align__(16) float w1l[64];
    __shared__ __align__(16) float be1s[64];
    __shared__ __align__(16) float We2t[512];   // [f][j] transposed
    __shared__ float be2s[8];

    const int tid = threadIdx.x;
    for (int i = tid; i < 64; i += 256) { w1l[i] = We1[8192 + i]; be1s[i] = be1[i]; }
    for (int i = tid; i < 512; i += 256) {
        int f = i >> 6, j = i & 63;
        We2t[i] = We2[j * 8 + f];
    }
    if (tid < 8) be2s[tid] = be2[tid];
    __syncthreads();

    const int l  = tid & 15;
    const int j0 = l * 4;
    const int grp = tid >> 4;

    const float4 wl = *reinterpret_cast<const float4*>(w1l + j0);
    const float4 bv = *reinterpret_cast<const float4*>(be1s + j0);

    for (int e0 = blockIdx.x * 64; e0 < E; e0 += gridDim.x * 64) {
        int s[4], d[4];
        bool act[4];
        float dist[4];
        float4 ga[4], gb[4];

        // issue all index loads
#pragma unroll
        for (int b = 0; b < 4; ++b) {
            int e = e0 + b * 16 + grp;
            act[b] = (e < E);
            int ix = act[b] ? e : (E - 1);
            s[b] = ei[ix];
            d[b] = ei[E + ix];
        }
        // issue all gathers + pos loads
#pragma unroll
        for (int b = 0; b < 4; ++b) {
            ga[b] = *reinterpret_cast<const float4*>(g_xW + (size_t)s[b] * 64 + j0);
            gb[b] = *reinterpret_cast<const float4*>(g_xW + (size_t)d[b] * 64 + j0);
        }
#pragma unroll
        for (int b = 0; b < 4; ++b) {
            float dx = pos[s[b] * 3 + 0] - pos[d[b] * 3 + 0];
            float dy = pos[s[b] * 3 + 1] - pos[d[b] * 3 + 1];
            float dz = pos[s[b] * 3 + 2] - pos[d[b] * 3 + 2];
            dist[b] = sqrtf(dx * dx + dy * dy + dz * dz);
        }

        // compute + reduce + store per edge
#pragma unroll
        for (int b = 0; b < 4; ++b) {
            float h0 = fmaxf(fmaf(dist[b], wl.x, ga[b].x + gb[b].x) + bv.x, 0.0f);
            float h1 = fmaxf(fmaf(dist[b], wl.y, ga[b].y + gb[b].y) + bv.y, 0.0f);
            float h2 = fmaxf(fmaf(dist[b], wl.z, ga[b].z + gb[b].z) + bv.z, 0.0f);
            float h3 = fmaxf(fmaf(dist[b], wl.w, ga[b].w + gb[b].w) + bv.w, 0.0f);
            float fe[8];
#pragma unroll
            for (int f = 0; f < 8; ++f) {
                float4 w = *reinterpret_cast<const float4*>(We2t + f * 64 + j0);
                float acc = h0 * w.x;
                acc = fmaf(h1, w.y, acc);
                acc = fmaf(h2, w.z, acc);
                fe[f] = fmaf(h3, w.w, acc);
            }
            edge_reduce_and_store(fe, l, s[b], d[b], act[b], be2s);
        }
    }
}

// ---------------------------------------------------------------------------
// Fused per-graph vertex reduce + f1
// ---------------------------------------------------------------------------
__global__ __launch_bounds__(256) void vreduce_f1_kernel(
    const int* __restrict__ vs, const int* __restrict__ es,
    const float* __restrict__ Wd0, const float* __restrict__ bd0,
    const float* __restrict__ Wd1, const float* __restrict__ bd1)
{
    __shared__ float rn[8], rx[8];
    const int tid = threadIdx.x, g = blockIdx.x;
    const int v0 = vs[g], v1 = vs[g + 1];
    if (tid < 8) { rn[tid] = 0.0f; rx[tid] = 0.0f; }
    __syncthreads();

    float ln[8], lx[8];
#pragma unroll
    for (int f = 0; f < 8; ++f) { ln[f] = 0.0f; lx[f] = 0.0f; }
    for (int v = v0 + tid; v < v1; v += 256) {
        const int4* mn = reinterpret_cast<const int4*>(g_mink + (size_t)v * 8);
        const int4* mx = reinterpret_cast<const int4*>(g_maxk + (size_t)v * 8);
        int4 a = mn[0], b = mn[1], c = mx[0], d = mx[1];
        ln[0] += (a.x == 0x7f800000) ? 1.0f : __int_as_float(a.x);
        ln[1] += (a.y == 0x7f800000) ? 1.0f : __int_as_float(a.y);
        ln[2] += (a.z == 0x7f800000) ? 1.0f : __int_as_float(a.z);
        ln[3] += (a.w == 0x7f800000) ? 1.0f : __int_as_float(a.w);
        ln[4] += (b.x == 0x7f800000) ? 1.0f : __int_as_float(b.x);
        ln[5] += (b.y == 0x7f800000) ? 1.0f : __int_as_float(b.y);
        ln[6] += (b.z == 0x7f800000) ? 1.0f : __int_as_float(b.z);
        ln[7] += (b.w == 0x7f800000) ? 1.0f : __int_as_float(b.w);
        lx[0] += (c.x == 0) ? 1.0f : __int_as_float(c.x);
        lx[1] += (c.y == 0) ? 1.0f : __int_as_float(c.y);
        lx[2] += (c.z == 0) ? 1.0f : __int_as_float(c.z);
        lx[3] += (c.w == 0) ? 1.0f : __int_as_float(c.w);
        lx[4] += (d.x == 0) ? 1.0f : __int_as_float(d.x);
        lx[5] += (d.y == 0) ? 1.0f : __int_as_float(d.y);
        lx[6] += (d.z == 0) ? 1.0f : __int_as_float(d.z);
        lx[7] += (d.w == 0) ? 1.0f : __int_as_float(d.w);
    }
    const unsigned m = 0xffffffffu;
    int lane = tid & 31;
#pragma unroll
    for (int f = 0; f < 8; ++f) {
        float s = ln[f];
        s += __shfl_xor_sync(m, s, 16); s += __shfl_xor_sync(m, s, 8);
        s += __shfl_xor_sync(m, s, 4);  s += __shfl_xor_sync(m, s, 2);
        s += __shfl_xor_sync(m, s, 1);
        if (lane == 0) atomicAdd(&rn[f], s);
        float t = lx[f];
        t += __shfl_xor_sync(m, t, 16); t += __shfl_xor_sync(m, t, 8);
        t += __shfl_xor_sync(m, t, 4);  t += __shfl_xor_sync(m, t, 2);
        t += __shfl_xor_sync(m, t, 1);
        if (lane == 0) atomicAdd(&rx[f], t);
    }
    __syncthreads();

    if (tid < 64) {
        int o = tid;
        float a = 0.0f;
#pragma unroll
        for (int f = 0; f < 8; ++f) {
            a = fmaf(g_Sfv[g * 8 + f], Wd0[(4 * f + 1) * 64 + o], a);
            a = fmaf(rx[f],            Wd0[(4 * f + 2) * 64 + o], a);
            a = fmaf(rn[f],            Wd0[(4 * f + 3) * 64 + o], a);
        }
        int nv = v1 - v0;
        int ne = es[g + 1] - es[g];
        float x0 = a / (float)nv + bd0[o];
        float x1 = (ne - (nv - 1) > 0)
                       ? (Wd1[64 + o] + Wd1[128 + o] + Wd1[192 + o] + bd1[o])
                       : 0.0f;
        g_h[g * 64 + o] = x0 + x1;
    }
}

// BatchNorm stats (two-pass)
__global__ void bn_kernel(int G)
{
    __shared__ float ps[512];
    __shared__ float mu_s[64];
    int t = threadIdx.x, o = t & 63, grp = t >> 6;
    float s = 0.0f;
    for (int r = grp; r < G; r += 8) s += g_h[r * 64 + o];
    ps[t] = s;
    __syncthreads();
    if (t < 64) {
        float S = 0.0f;
        for (int k = 0; k < 8; ++k) S += ps[k * 64 + o];
        mu_s[o] = S / (float)G;
    }
    __syncthreads();
    float mu = mu_s[o];
    s = 0.0f;
    for (int r = grp; r < G; r += 8) { float d = g_h[r * 64 + o] - mu; s = fmaf(d, d, s); }
    ps[t] = s;
    __syncthreads();
    if (t < 64) {
        float S = 0.0f;
        for (int k = 0; k < 8; ++k) S += ps[k * 64 + o];
        g_bn[o] = mu_s[o];
        g_bn[64 + o] = rsqrtf(S / (float)G + 1e-5f);
    }
}

// normalize + out MLP
__global__ __launch_bounds__(1024) void out_kernel(
    const float* __restrict__ gamma, const float* __restrict__ beta,
    const float* __restrict__ Wo1, const float* __restrict__ bo1,
    const float* __restrict__ Wo2, const float* __restrict__ bo2,
    float* __restrict__ out, int G)
{
    __shared__ float hn[16][64];
    __shared__ float t1[16][64];
    int t = threadIdx.x, gl = t >> 6, o = t & 63;
    int g = blockIdx.x * 16 + gl;
    float v = 0.0f;
    if (g < G) v = (g_h[g * 64 + o] - g_bn[o]) * g_bn[64 + o] * gamma[o] + beta[o];
    hn[gl][o] = v;
    __syncthreads();
    float a = bo1[o];
#pragma unroll 8
    for (int k = 0; k < 64; ++k) a = fmaf(hn[gl][k], Wo1[k * 64 + o], a);
    t1[gl][o] = fmaxf(a, 0.0f);
    __syncthreads();
    float b = bo2[o];
#pragma unroll 8
    for (int k = 0; k < 64; ++k) b = fmaf(t1[gl][k], Wo2[k * 64 + o], b);
    if (g < G) out[g * 64 + o] = b;
}

extern "C" void kernel_launch(void* const* d_in, const int* in_sizes, int n_in,
                              void* d_out, int out_size)
{
    const float* x     = (const float*)d_in[0];
    const float* pos   = (const float*)d_in[1];
    const int*   ei    = (const int*)d_in[2];
    const int*   vs    = (const int*)d_in[3];
    const int*   es    = (const int*)d_in[4];
    const int*   batch = (const int*)d_in[5];
    const float* W1  = (const float*)d_in[6];
    const float* b1  = (const float*)d_in[7];
    const float* W2  = (const float*)d_in[8];
    const float* b2  = (const float*)d_in[9];
    const float* We1 = (const float*)d_in[10];
    const float* be1 = (const float*)d_in[11];
    const float* We2 = (const float*)d_in[12];
    const float* be2 = (const float*)d_in[13];
    const float* Wd0 = (const float*)d_in[14];
    const float* bd0 = (const float*)d_in[15];
    const float* Wd1 = (const float*)d_in[16];
    const float* bd1 = (const float*)d_in[17];
    const float* gm  = (const float*)d_in[18];
    const float* bt  = (const float*)d_in[19];
    const float* Wo1 = (const float*)d_in[20];
    const float* bo1 = (const float*)d_in[21];
    const float* Wo2 = (const float*)d_in[22];
    const float* bo2 = (const float*)d_in[23];

    int N = in_sizes[0] / 128;
    int E = in_sizes[2] / 2;
    int G = out_size / 64;
    int tiles = (N + 127) / 128;

    init_kernel<<<(N * 8 + 255) / 256, 256>>>(N * 8, G * 8);   // launch 1
    spacer_kernel<<<1, 32>>>();                                 // launch 2

    size_t smv = (size_t)SMV_FLOATS * sizeof(float);
    cudaFuncSetAttribute(vertex_kernel, cudaFuncAttributeMaxDynamicSharedMemorySize, (int)smv);
    vertex_kernel<<<148, 512, smv>>>(x, batch, W1, b1, W2, b2, We1, N, tiles); // launch 3

    edge_kernel<<<2048, 256>>>(pos, ei, We1, be1, We2, be2, E); // launch 4 (ncu slot)
    vreduce_f1_kernel<<<G, 256>>>(vs, es, Wd0, bd0, Wd1, bd1);
    bn_kernel<<<1, 512>>>(G);
    out_kernel<<<(G + 15) / 16, 1024>>>(gm, bt, Wo1, bo1, Wo2, bo2, (float*)d_out, G);
}

// round 16
// speedup vs baseline: 1.4891x; 1.0333x over previous
#include <cuda_runtime.h>
#include <cstdint>
#include <cstddef>
#include <math.h>

#define NMAX 204800
#define GMAX 512

// ---- scratch (no allocations allowed) ----
__device__ __align__(16) float g_xW[(size_t)NMAX * 64]; // per-vertex x @ We1[:128] (raw)
__device__ __align__(16) int   g_mink[(size_t)NMAX * 8];
__device__ __align__(16) int   g_maxk[(size_t)NMAX * 8];
__device__ float g_Sfv[GMAX * 8];
__device__ float g_h[GMAX * 64];
__device__ float g_bn[128];

__device__ __forceinline__ float sigmoidf_(float x) {
    return 1.0f / (1.0f + __expf(-x));
}

__device__ __forceinline__ unsigned long long pack2(float lo, float hi) {
    unsigned long long r;
    asm("mov.b64 %0, {%1, %2};" : "=l"(r) : "f"(lo), "f"(hi));
    return r;
}
__device__ __forceinline__ void unpack2(unsigned long long v, float& lo, float& hi) {
    asm("mov.b64 {%0, %1}, %2;" : "=f"(lo), "=f"(hi) : "l"(v));
}
__device__ __forceinline__ unsigned long long ffma2(unsigned long long a,
                                                    unsigned long long b,
                                                    unsigned long long c) {
    unsigned long long d;
    asm("fma.rn.f32x2 %0, %1, %2, %3;" : "=l"(d) : "l"(a), "l"(b), "l"(c));
    return d;
}

__device__ __forceinline__ void cp_async16(unsigned dst, const void* src, int nbytes) {
    asm volatile("cp.async.cg.shared.global [%0], [%1], 16, %2;"
                 :: "r"(dst), "l"(src), "r"(nbytes));
}
#define CP_COMMIT() asm volatile("cp.async.commit_group;" ::: "memory")
#define CP_WAIT0()  asm volatile("cp.async.wait_group 0;" ::: "memory")

// init sentinels + Sfv (vectorized)
__global__ void init_kernel(int n2, int g8) {
    int i = blockIdx.x * blockDim.x + threadIdx.x;
    if (i < n2) {
        reinterpret_cast<int4*>(g_mink)[i] =
            make_int4(0x7f800000, 0x7f800000, 0x7f800000, 0x7f800000);
        reinterpret_cast<int4*>(g_maxk)[i] = make_int4(0, 0, 0, 0);
    }
    if (i < g8) g_Sfv[i] = 0.0f;
}

// no-op spacers so ncu's fixed capture slot (4th launch) lands on vertex_kernel
__global__ void spacer_kernel() {}
__global__ void spacer2_kernel() {}

// ---------------------------------------------------------------------------
// Persistent vertex kernel (R9 config + R16: hoisted loop-head load batch,
// k4 unrolled x4 for a wide scheduling window).
// ---------------------------------------------------------------------------
#define XS_STRIDE 132
#define XS_FLOATS (128 * XS_STRIDE)      // 16896
#define W_OFF     (2 * XS_FLOATS)        // 33792
#define W2_OFF    (W_OFF + 16384)        // 50176
#define B1_OFF    (W2_OFF + 512)
#define B2_OFF    (B1_OFF + 64)
#define SMV_FLOATS (B2_OFF + 8)          // 50760 floats = 203040 B

__device__ __forceinline__ void prefetch_tile(const float* __restrict__ x,
                                              int v0, int N,
                                              unsigned xs_sm, int tid) {
#pragma unroll
    for (int i = 0; i < 8; ++i) {
        int c = tid + i * 512;
        int row = c >> 5, col4 = c & 31;
        unsigned dst = xs_sm + (unsigned)(row * XS_STRIDE + col4 * 4) * 4u;
        const float* src = x + (size_t)(v0 + row) * 128 + col4 * 4;
        int nb = (v0 + row < N) ? 16 : 0;
        cp_async16(dst, src, nb);
    }
}

__global__ __launch_bounds__(512) void vertex_kernel(
    const float* __restrict__ x, const int* __restrict__ batch,
    const float* __restrict__ W1, const float* __restrict__ b1,
    const float* __restrict__ W2, const float* __restrict__ b2,
    const float* __restrict__ We1, int N, int tiles)
{
    extern __shared__ float sm[];
    float* Wsm = sm + W_OFF;
    float* W2s = sm + W2_OFF;
    float* b1s = sm + B1_OFF;
    float* b2s = sm + B2_OFF;

    const int tid = threadIdx.x;
    const unsigned sm_base = (unsigned)__cvta_generic_to_shared(sm);

    for (int i = tid; i < 16384; i += 512) {
        int k = i >> 7, n = i & 127;
        Wsm[i] = (n < 64) ? W1[k * 64 + n] : We1[k * 64 + (n - 64)];
    }
    if (tid < 512) W2s[tid] = W2[tid];
    if (tid < 64) b1s[tid] = b1[tid];
    if (tid < 8)  b2s[tid] = b2[tid];

    const int stride = gridDim.x;
    int pp = 0;
    if ((int)blockIdx.x < tiles)
        prefetch_tile(x, blockIdx.x * 128, N, sm_base, tid);
    CP_COMMIT();
    __syncthreads();

    const int tx = tid & 31;
    const int ty = tid >> 5;
    const int m0 = ty * 8, n0 = tx * 4;

    for (int t = blockIdx.x; t < tiles; t += stride) {
        CP_WAIT0();
        __syncthreads();

        int tn = t + stride;
        if (tn < tiles)
            prefetch_tile(x, tn * 128, N,
                          sm_base + (unsigned)((pp ^ 1) * XS_FLOATS) * 4u, tid);
        CP_COMMIT();

        float* xs   = sm + pp * XS_FLOATS;
        float* hbuf = xs;
        const int v0 = t * 128;

        unsigned long long acc[8][2];
#pragma unroll
        for (int mi = 0; mi < 8; ++mi) { acc[mi][0] = 0ULL; acc[mi][1] = 0ULL; }

#pragma unroll 4
        for (int k4 = 0; k4 < 128; k4 += 4) {
            // loop-head load batch: 8 broadcast xr + 4 unique-per-lane W
            float4 xr[8];
#pragma unroll
            for (int mi = 0; mi < 8; ++mi)
                xr[mi] = *reinterpret_cast<const float4*>(
                    xs + (m0 + mi) * XS_STRIDE + k4);
            float4 wa[4];
#pragma unroll
            for (int kk = 0; kk < 4; ++kk)
                wa[kk] = *reinterpret_cast<const float4*>(
                    Wsm + ((k4 + kk) << 7) + n0);

#pragma unroll
            for (int kk = 0; kk < 4; ++kk) {
                unsigned long long w0  = pack2(wa[kk].x, wa[kk].y);
                unsigned long long w1p = pack2(wa[kk].z, wa[kk].w);
#pragma unroll
                for (int mi = 0; mi < 8; ++mi) {
                    float xv = (kk == 0) ? xr[mi].x
                             : (kk == 1) ? xr[mi].y
                             : (kk == 2) ? xr[mi].z : xr[mi].w;
                    unsigned long long xx = pack2(xv, xv);
                    acc[mi][0] = ffma2(xx, w0,  acc[mi][0]);
                    acc[mi][1] = ffma2(xx, w1p, acc[mi][1]);
                }
            }
        }
        __syncthreads();

        if (tx < 16) {
#pragma unroll
            for (int mi = 0; mi < 8; ++mi) {
                float* dst = hbuf + (m0 + mi) * XS_STRIDE + n0;
                float l0, h0, l1, h1;
                unpack2(acc[mi][0], l0, h0);
                unpack2(acc[mi][1], l1, h1);
                dst[0] = l0; dst[1] = h0; dst[2] = l1; dst[3] = h1;
            }
        } else {
#pragma unroll
            for (int mi = 0; mi < 8; ++mi) {
                int v = v0 + m0 + mi;
                if (v < N) {
                    float l0, h0, l1, h1;
                    unpack2(acc[mi][0], l0, h0);
                    unpack2(acc[mi][1], l1, h1);
                    *reinterpret_cast<float4*>(g_xW + (size_t)v * 64 + (n0 - 64)) =
                        make_float4(l0, h0, l1, h1);
                }
            }
        }
        __syncthreads();

        // fv epilogue: one vertex per thread (tid<128), float4 hbuf reads
        if (tid < 128) {
            int v = v0 + tid;
            bool valid = (v < N);
            float a8[8];
#pragma unroll
            for (int f = 0; f < 8; ++f) a8[f] = b2s[f];
            const float4* hr4 = reinterpret_cast<const float4*>(hbuf + tid * XS_STRIDE);
#pragma unroll 4
            for (int kq = 0; kq < 16; ++kq) {
                float4 hv4 = hr4[kq];
                int k = kq * 4;
                float hv0 = fmaxf(hv4.x + b1s[k + 0], 0.0f);
                float hv1 = fmaxf(hv4.y + b1s[k + 1], 0.0f);
                float hv2 = fmaxf(hv4.z + b1s[k + 2], 0.0f);
                float hv3 = fmaxf(hv4.w + b1s[k + 3], 0.0f);
                const float* w0 = W2s + k * 8;
#pragma unroll
                for (int f = 0; f < 8; ++f) {
                    float acc = fmaf(hv0, w0[f], a8[f]);
                    acc = fmaf(hv1, w0[8 + f], acc);
                    acc = fmaf(hv2, w0[16 + f], acc);
                    a8[f] = fmaf(hv3, w0[24 + f], acc);
                }
            }
#pragma unroll
            for (int f = 0; f < 8; ++f) a8[f] = valid ? sigmoidf_(a8[f]) : 0.0f;

            const unsigned m = 0xffffffffu;
            int lane = tid & 31;
            int gidx = batch[valid ? v : (N - 1)];
            int gl0  = __shfl_sync(m, gidx, 0);
            bool uni = __all_sync(m, gidx == gl0);
            if (uni) {
#pragma unroll
                for (int f = 0; f < 8; ++f) {
                    float s = a8[f];
                    s += __shfl_xor_sync(m, s, 16);
                    s += __shfl_xor_sync(m, s, 8);
                    s += __shfl_xor_sync(m, s, 4);
                    s += __shfl_xor_sync(m, s, 2);
                    s += __shfl_xor_sync(m, s, 1);
                    if (lane == 0) atomicAdd(&g_Sfv[gl0 * 8 + f], s);
                }
            } else if (valid) {
#pragma unroll
                for (int f = 0; f < 8; ++f) atomicAdd(&g_Sfv[gidx * 8 + f], a8[f]);
            }
        }
        pp ^= 1;
    }
}

// ---------------------------------------------------------------------------
// Edge kernel (R15 config — best measured: 70us): 16 lanes/edge, 4 edges per
// group per iteration, transposed We2, channel-scattering butterfly.
// ---------------------------------------------------------------------------
__device__ __forceinline__ void edge_reduce_and_store(
    float fe[8], int l, int s, int d, bool active, const float* be2s)
{
    const unsigned fullm = 0xffffffffu;
#pragma unroll
    for (int f = 0; f < 8; ++f)
        fe[f] += __shfl_xor_sync(fullm, fe[f], 8);
    const bool kb2 = (l >> 2) & 1;
    float g4[4];
#pragma unroll
    for (int i = 0; i < 4; ++i) {
        float send = kb2 ? fe[i] : fe[i + 4];
        float recv = __shfl_xor_sync(fullm, send, 4);
        g4[i] = (kb2 ? fe[i + 4] : fe[i]) + recv;
    }
    const bool kb1 = (l >> 1) & 1;
    float g2[2];
#pragma unroll
    for (int i = 0; i < 2; ++i) {
        float send = kb1 ? g4[i] : g4[i + 2];
        float recv = __shfl_xor_sync(fullm, send, 2);
        g2[i] = (kb1 ? g4[i + 2] : g4[i]) + recv;
    }
    const bool kb0 = l & 1;
    float send = kb0 ? g2[0] : g2[1];
    float recv = __shfl_xor_sync(fullm, send, 1);
    float tot = (kb0 ? g2[1] : g2[0]) + recv;
    int c = l & 7;
    int vtx = (l < 8) ? s : d;
    int key = __float_as_int(sigmoidf_(tot + be2s[c]));
    if (active) {
        atomicMin(g_mink + (size_t)vtx * 8 + c, key);
        atomicMax(g_maxk + (size_t)vtx * 8 + c, key);
    }
}

__global__ __launch_bounds__(256, 2) void edge_kernel(
    const float* __restrict__ pos, const int* __restrict__ ei,
    const float* __restrict__ We1, const float* __restrict__ be1,
    const float* __restrict__ We2, const float* __restrict__ be2, int E)
{
    __shared__ __align__(16) float w1l[64];
    __shared__ __align__(16) float be1s[64];
    __shared__ __align__(16) float We2t[512];   // [f][j] transposed
    __shared__ float be2s[8];

    const int tid = threadIdx.x;
    for (int i = tid; i < 64; i += 256) { w1l[i] = We1[8192 + i]; be1s[i] = be1[i]; }
    for (int i = tid; i < 512; i += 256) {
        int f = i >> 6, j = i & 63;
        We2t[i] = We2[j * 8 + f];
    }
    if (tid < 8) be2s[tid] = be2[tid];
    __syncthreads();

    const int l  = tid & 15;
    const int j0 = l * 4;
    const int grp = tid >> 4;

    const float4 wl = *reinterpret_cast<const float4*>(w1l + j0);
    const float4 bv = *reinterpret_cast<const float4*>(be1s + j0);

    for (int e0 = blockIdx.x * 64; e0 < E; e0 += gridDim.x * 64) {
        int s[4], d[4];
        bool act[4];
        float dist[4];
        float4 ga[4], gb[4];

#pragma unroll
        for (int b = 0; b < 4; ++b) {
            int e = e0 + b * 16 + grp;
            act[b] = (e < E);
            int ix = act[b] ? e : (E - 1);
            s[b] = ei[ix];
            d[b] = ei[E + ix];
        }
#pragma unroll
        for (int b = 0; b < 4; ++b) {
            ga[b] = *reinterpret_cast<const float4*>(g_xW + (size_t)s[b] * 64 + j0);
            gb[b] = *reinterpret_cast<const float4*>(g_xW + (size_t)d[b] * 64 + j0);
        }
#pragma unroll
        for (int b = 0; b < 4; ++b) {
            float dx = pos[s[b] * 3 + 0] - pos[d[b] * 3 + 0];
            float dy = pos[s[b] * 3 + 1] - pos[d[b] * 3 + 1];
            float dz = pos[s[b] * 3 + 2] - pos[d[b] * 3 + 2];
            dist[b] = sqrtf(dx * dx + dy * dy + dz * dz);
        }

#pragma unroll
        for (int b = 0; b < 4; ++b) {
            float h0 = fmaxf(fmaf(dist[b], wl.x, ga[b].x + gb[b].x) + bv.x, 0.0f);
            float h1 = fmaxf(fmaf(dist[b], wl.y, ga[b].y + gb[b].y) + bv.y, 0.0f);
            float h2 = fmaxf(fmaf(dist[b], wl.z, ga[b].z + gb[b].z) + bv.z, 0.0f);
            float h3 = fmaxf(fmaf(dist[b], wl.w, ga[b].w + gb[b].w) + bv.w, 0.0f);
            float fe[8];
#pragma unroll
            for (int f = 0; f < 8; ++f) {
                float4 w = *reinterpret_cast<const float4*>(We2t + f * 64 + j0);
                float acc = h0 * w.x;
                acc = fmaf(h1, w.y, acc);
                acc = fmaf(h2, w.z, acc);
                fe[f] = fmaf(h3, w.w, acc);
            }
            edge_reduce_and_store(fe, l, s[b], d[b], act[b], be2s);
        }
    }
}

// ---------------------------------------------------------------------------
// Fused per-graph vertex reduce + f1
// ---------------------------------------------------------------------------
__global__ __launch_bounds__(256) void vreduce_f1_kernel(
    const int* __restrict__ vs, const int* __restrict__ es,
    const float* __restrict__ Wd0, const float* __restrict__ bd0,
    const float* __restrict__ Wd1, const float* __restrict__ bd1)
{
    __shared__ float rn[8], rx[8];
    const int tid = threadIdx.x, g = blockIdx.x;
    const int v0 = vs[g], v1 = vs[g + 1];
    if (tid < 8) { rn[tid] = 0.0f; rx[tid] = 0.0f; }
    __syncthreads();

    float ln[8], lx[8];
#pragma unroll
    for (int f = 0; f < 8; ++f) { ln[f] = 0.0f; lx[f] = 0.0f; }
    for (int v = v0 + tid; v < v1; v += 256) {
        const int4* mn = reinterpret_cast<const int4*>(g_mink + (size_t)v * 8);
        const int4* mx = reinterpret_cast<const int4*>(g_maxk + (size_t)v * 8);
        int4 a = mn[0], b = mn[1], c = mx[0], d = mx[1];
        ln[0] += (a.x == 0x7f800000) ? 1.0f : __int_as_float(a.x);
        ln[1] += (a.y == 0x7f800000) ? 1.0f : __int_as_float(a.y);
        ln[2] += (a.z == 0x7f800000) ? 1.0f : __int_as_float(a.z);
        ln[3] += (a.w == 0x7f800000) ? 1.0f : __int_as_float(a.w);
        ln[4] += (b.x == 0x7f800000) ? 1.0f : __int_as_float(b.x);
        ln[5] += (b.y == 0x7f800000) ? 1.0f : __int_as_float(b.y);
        ln[6] += (b.z == 0x7f800000) ? 1.0f : __int_as_float(b.z);
        ln[7] += (b.w == 0x7f800000) ? 1.0f : __int_as_float(b.w);
        lx[0] += (c.x == 0) ? 1.0f : __int_as_float(c.x);
        lx[1] += (c.y == 0) ? 1.0f : __int_as_float(c.y);
        lx[2] += (c.z == 0) ? 1.0f : __int_as_float(c.z);
        lx[3] += (c.w == 0) ? 1.0f : __int_as_float(c.w);
        lx[4] += (d.x == 0) ? 1.0f : __int_as_float(d.x);
        lx[5] += (d.y == 0) ? 1.0f : __int_as_float(d.y);
        lx[6] += (d.z == 0) ? 1.0f : __int_as_float(d.z);
        lx[7] += (d.w == 0) ? 1.0f : __int_as_float(d.w);
    }
    const unsigned m = 0xffffffffu;
    int lane = tid & 31;
#pragma unroll
    for (int f = 0; f < 8; ++f) {
        float s = ln[f];
        s += __shfl_xor_sync(m, s, 16); s += __shfl_xor_sync(m, s, 8);
        s += __shfl_xor_sync(m, s, 4);  s += __shfl_xor_sync(m, s, 2);
        s += __shfl_xor_sync(m, s, 1);
        if (lane == 0) atomicAdd(&rn[f], s);
        float t = lx[f];
        t += __shfl_xor_sync(m, t, 16); t += __shfl_xor_sync(m, t, 8);
        t += __shfl_xor_sync(m, t, 4);  t += __shfl_xor_sync(m, t, 2);
        t += __shfl_xor_sync(m, t, 1);
        if (lane == 0) atomicAdd(&rx[f], t);
    }
    __syncthreads();

    if (tid < 64) {
        int o = tid;
        float a = 0.0f;
#pragma unroll
        for (int f = 0; f < 8; ++f) {
            a = fmaf(g_Sfv[g * 8 + f], Wd0[(4 * f + 1) * 64 + o], a);
            a = fmaf(rx[f],            Wd0[(4 * f + 2) * 64 + o], a);
            a = fmaf(rn[f],            Wd0[(4 * f + 3) * 64 + o], a);
        }
        int nv = v1 - v0;
        int ne = es[g + 1] - es[g];
        float x0 = a / (float)nv + bd0[o];
        float x1 = (ne - (nv - 1) > 0)
                       ? (Wd1[64 + o] + Wd1[128 + o] + Wd1[192 + o] + bd1[o])
                       : 0.0f;
        g_h[g * 64 + o] = x0 + x1;
    }
}

// BatchNorm stats (two-pass)
__global__ void bn_kernel(int G)
{
    __shared__ float ps[512];
    __shared__ float mu_s[64];
    int t = threadIdx.x, o = t & 63, grp = t >> 6;
    float s = 0.0f;
    for (int r = grp; r < G; r += 8) s += g_h[r * 64 + o];
    ps[t] = s;
    __syncthreads();
    if (t < 64) {
        float S = 0.0f;
        for (int k = 0; k < 8; ++k) S += ps[k * 64 + o];
        mu_s[o] = S / (float)G;
    }
    __syncthreads();
    float mu = mu_s[o];
    s = 0.0f;
    for (int r = grp; r < G; r += 8) { float d = g_h[r * 64 + o] - mu; s = fmaf(d, d, s); }
    ps[t] = s;
    __syncthreads();
    if (t < 64) {
        float S = 0.0f;
        for (int k = 0; k < 8; ++k) S += ps[k * 64 + o];
        g_bn[o] = mu_s[o];
        g_bn[64 + o] = rsqrtf(S / (float)G + 1e-5f);
    }
}

// normalize + out MLP
__global__ __launch_bounds__(1024) void out_kernel(
    const float* __restrict__ gamma, const float* __restrict__ beta,
    const float* __restrict__ Wo1, const float* __restrict__ bo1,
    const float* __restrict__ Wo2, const float* __restrict__ bo2,
    float* __restrict__ out, int G)
{
    __shared__ float hn[16][64];
    __shared__ float t1[16][64];
    int t = threadIdx.x, gl = t >> 6, o = t & 63;
    int g = blockIdx.x * 16 + gl;
    float v = 0.0f;
    if (g < G) v = (g_h[g * 64 + o] - g_bn[o]) * g_bn[64 + o] * gamma[o] + beta[o];
    hn[gl][o] = v;
    __syncthreads();
    float a = bo1[o];
#pragma unroll 8
    for (int k = 0; k < 64; ++k) a = fmaf(hn[gl][k], Wo1[k * 64 + o], a);
    t1[gl][o] = fmaxf(a, 0.0f);
    __syncthreads();
    float b = bo2[o];
#pragma unroll 8
    for (int k = 0; k < 64; ++k) b = fmaf(t1[gl][k], Wo2[k * 64 + o], b);
    if (g < G) out[g * 64 + o] = b;
}

extern "C" void kernel_launch(void* const* d_in, const int* in_sizes, int n_in,
                              void* d_out, int out_size)
{
    const float* x     = (const float*)d_in[0];
    const float* pos   = (const float*)d_in[1];
    const int*   ei    = (const int*)d_in[2];
    const int*   vs    = (const int*)d_in[3];
    const int*   es    = (const int*)d_in[4];
    const int*   batch = (const int*)d_in[5];
    const float* W1  = (const float*)d_in[6];
    const float* b1  = (const float*)d_in[7];
    const float* W2  = (const float*)d_in[8];
    const float* b2  = (const float*)d_in[9];
    const float* We1 = (const float*)d_in[10];
    const float* be1 = (const float*)d_in[11];
    const float* We2 = (const float*)d_in[12];
    const float* be2 = (const float*)d_in[13];
    const float* Wd0 = (const float*)d_in[14];
    const float* bd0 = (const float*)d_in[15];
    const float* Wd1 = (const float*)d_in[16];
    const float* bd1 = (const float*)d_in[17];
    const float* gm  = (const float*)d_in[18];
    const float* bt  = (const float*)d_in[19];
    const float* Wo1 = (const float*)d_in[20];
    const float* bo1 = (const float*)d_in[21];
    const float* Wo2 = (const float*)d_in[22];
    const float* bo2 = (const float*)d_in[23];

    int N = in_sizes[0] / 128;
    int E = in_sizes[2] / 2;
    int G = out_size / 64;
    int tiles = (N + 127) / 128;

    init_kernel<<<(N * 2 + 255) / 256, 256>>>(N * 2, G * 8);   // launch 1
    spacer_kernel<<<1, 32>>>();                                 // launch 2
    spacer2_kernel<<<1, 32>>>();                                // launch 3

    size_t smv = (size_t)SMV_FLOATS * sizeof(float);
    cudaFuncSetAttribute(vertex_kernel, cudaFuncAttributeMaxDynamicSharedMemorySize, (int)smv);
    vertex_kernel<<<148, 512, smv>>>(x, batch, W1, b1, W2, b2, We1, N, tiles); // launch 4 (ncu slot)

    edge_kernel<<<2048, 256>>>(pos, ei, We1, be1, We2, be2, E);
    vreduce_f1_kernel<<<G, 256>>>(vs, es, Wd0, bd0, Wd1, bd1);
    bn_kernel<<<1, 512>>>(G);
    out_kernel<<<(G + 15) / 16, 1024>>>(gm, bt, Wo1, bo1, Wo2, bo2, (float*)d_out, G);
}

// round 17
// speedup vs baseline: 1.5099x; 1.0140x over previous
#include <cuda_runtime.h>
#include <cstdint>
#include <cstddef>
#include <math.h>

#define NMAX 204800
#define GMAX 512

// ---- scratch (no allocations allowed) ----
__device__ __align__(16) float g_xW[(size_t)NMAX * 64]; // per-vertex x @ We1[:128] (raw)
__device__ __align__(16) int   g_mink[(size_t)NMAX * 8];
__device__ __align__(16) int   g_maxk[(size_t)NMAX * 8];
__device__ float g_Sfv[GMAX * 8];
__device__ float g_h[GMAX * 64];

__device__ __forceinline__ float sigmoidf_(float x) {
    return 1.0f / (1.0f + __expf(-x));
}

__device__ __forceinline__ unsigned long long pack2(float lo, float hi) {
    unsigned long long r;
    asm("mov.b64 %0, {%1, %2};" : "=l"(r) : "f"(lo), "f"(hi));
    return r;
}
__device__ __forceinline__ void unpack2(unsigned long long v, float& lo, float& hi) {
    asm("mov.b64 {%0, %1}, %2;" : "=f"(lo), "=f"(hi) : "l"(v));
}
__device__ __forceinline__ unsigned long long ffma2(unsigned long long a,
                                                    unsigned long long b,
                                                    unsigned long long c) {
    unsigned long long d;
    asm("fma.rn.f32x2 %0, %1, %2, %3;" : "=l"(d) : "l"(a), "l"(b), "l"(c));
    return d;
}

__device__ __forceinline__ void cp_async16(unsigned dst, const void* src, int nbytes) {
    asm volatile("cp.async.cg.shared.global [%0], [%1], 16, %2;"
                 :: "r"(dst), "l"(src), "r"(nbytes));
}
#define CP_COMMIT() asm volatile("cp.async.commit_group;" ::: "memory")
#define CP_WAIT0()  asm volatile("cp.async.wait_group 0;" ::: "memory")

// init sentinels + Sfv (vectorized)
__global__ void init_kernel(int n2, int g8) {
    int i = blockIdx.x * blockDim.x + threadIdx.x;
    if (i < n2) {
        reinterpret_cast<int4*>(g_mink)[i] =
            make_int4(0x7f800000, 0x7f800000, 0x7f800000, 0x7f800000);
        reinterpret_cast<int4*>(g_maxk)[i] = make_int4(0, 0, 0, 0);
    }
    if (i < g8) g_Sfv[i] = 0.0f;
}

// ---------------------------------------------------------------------------
// Persistent vertex kernel (R16 config — best measured: 171us).
// ---------------------------------------------------------------------------
#define XS_STRIDE 132
#define XS_FLOATS (128 * XS_STRIDE)      // 16896
#define W_OFF     (2 * XS_FLOATS)        // 33792
#define W2_OFF    (W_OFF + 16384)        // 50176
#define B1_OFF    (W2_OFF + 512)
#define B2_OFF    (B1_OFF + 64)
#define SMV_FLOATS (B2_OFF + 8)          // 50760 floats = 203040 B

__device__ __forceinline__ void prefetch_tile(const float* __restrict__ x,
                                              int v0, int N,
                                              unsigned xs_sm, int tid) {
#pragma unroll
    for (int i = 0; i < 8; ++i) {
        int c = tid + i * 512;
        int row = c >> 5, col4 = c & 31;
        unsigned dst = xs_sm + (unsigned)(row * XS_STRIDE + col4 * 4) * 4u;
        const float* src = x + (size_t)(v0 + row) * 128 + col4 * 4;
        int nb = (v0 + row < N) ? 16 : 0;
        cp_async16(dst, src, nb);
    }
}

__global__ __launch_bounds__(512) void vertex_kernel(
    const float* __restrict__ x, const int* __restrict__ batch,
    const float* __restrict__ W1, const float* __restrict__ b1,
    const float* __restrict__ W2, const float* __restrict__ b2,
    const float* __restrict__ We1, int N, int tiles)
{
    extern __shared__ float sm[];
    float* Wsm = sm + W_OFF;
    float* W2s = sm + W2_OFF;
    float* b1s = sm + B1_OFF;
    float* b2s = sm + B2_OFF;

    const int tid = threadIdx.x;
    const unsigned sm_base = (unsigned)__cvta_generic_to_shared(sm);

    for (int i = tid; i < 16384; i += 512) {
        int k = i >> 7, n = i & 127;
        Wsm[i] = (n < 64) ? W1[k * 64 + n] : We1[k * 64 + (n - 64)];
    }
    if (tid < 512) W2s[tid] = W2[tid];
    if (tid < 64) b1s[tid] = b1[tid];
    if (tid < 8)  b2s[tid] = b2[tid];

    const int stride = gridDim.x;
    int pp = 0;
    if ((int)blockIdx.x < tiles)
        prefetch_tile(x, blockIdx.x * 128, N, sm_base, tid);
    CP_COMMIT();
    __syncthreads();

    const int tx = tid & 31;
    const int ty = tid >> 5;
    const int m0 = ty * 8, n0 = tx * 4;

    for (int t = blockIdx.x; t < tiles; t += stride) {
        CP_WAIT0();
        __syncthreads();

        int tn = t + stride;
        if (tn < tiles)
            prefetch_tile(x, tn * 128, N,
                          sm_base + (unsigned)((pp ^ 1) * XS_FLOATS) * 4u, tid);
        CP_COMMIT();

        float* xs   = sm + pp * XS_FLOATS;
        float* hbuf = xs;
        const int v0 = t * 128;

        unsigned long long acc[8][2];
#pragma unroll
        for (int mi = 0; mi < 8; ++mi) { acc[mi][0] = 0ULL; acc[mi][1] = 0ULL; }

#pragma unroll 4
        for (int k4 = 0; k4 < 128; k4 += 4) {
            float4 xr[8];
#pragma unroll
            for (int mi = 0; mi < 8; ++mi)
                xr[mi] = *reinterpret_cast<const float4*>(
                    xs + (m0 + mi) * XS_STRIDE + k4);
            float4 wa[4];
#pragma unroll
            for (int kk = 0; kk < 4; ++kk)
                wa[kk] = *reinterpret_cast<const float4*>(
                    Wsm + ((k4 + kk) << 7) + n0);

#pragma unroll
            for (int kk = 0; kk < 4; ++kk) {
                unsigned long long w0  = pack2(wa[kk].x, wa[kk].y);
                unsigned long long w1p = pack2(wa[kk].z, wa[kk].w);
#pragma unroll
                for (int mi = 0; mi < 8; ++mi) {
                    float xv = (kk == 0) ? xr[mi].x
                             : (kk == 1) ? xr[mi].y
                             : (kk == 2) ? xr[mi].z : xr[mi].w;
                    unsigned long long xx = pack2(xv, xv);
                    acc[mi][0] = ffma2(xx, w0,  acc[mi][0]);
                    acc[mi][1] = ffma2(xx, w1p, acc[mi][1]);
                }
            }
        }
        __syncthreads();

        if (tx < 16) {
#pragma unroll
            for (int mi = 0; mi < 8; ++mi) {
                float* dst = hbuf + (m0 + mi) * XS_STRIDE + n0;
                float l0, h0, l1, h1;
                unpack2(acc[mi][0], l0, h0);
                unpack2(acc[mi][1], l1, h1);
                dst[0] = l0; dst[1] = h0; dst[2] = l1; dst[3] = h1;
            }
        } else {
#pragma unroll
            for (int mi = 0; mi < 8; ++mi) {
                int v = v0 + m0 + mi;
                if (v < N) {
                    float l0, h0, l1, h1;
                    unpack2(acc[mi][0], l0, h0);
                    unpack2(acc[mi][1], l1, h1);
                    *reinterpret_cast<float4*>(g_xW + (size_t)v * 64 + (n0 - 64)) =
                        make_float4(l0, h0, l1, h1);
                }
            }
        }
        __syncthreads();

        // fv epilogue: one vertex per thread (tid<128), float4 hbuf reads
        if (tid < 128) {
            int v = v0 + tid;
            bool valid = (v < N);
            float a8[8];
#pragma unroll
            for (int f = 0; f < 8; ++f) a8[f] = b2s[f];
            const float4* hr4 = reinterpret_cast<const float4*>(hbuf + tid * XS_STRIDE);
#pragma unroll 4
            for (int kq = 0; kq < 16; ++kq) {
                float4 hv4 = hr4[kq];
                int k = kq * 4;
                float hv0 = fmaxf(hv4.x + b1s[k + 0], 0.0f);
                float hv1 = fmaxf(hv4.y + b1s[k + 1], 0.0f);
                float hv2 = fmaxf(hv4.z + b1s[k + 2], 0.0f);
                float hv3 = fmaxf(hv4.w + b1s[k + 3], 0.0f);
                const float* w0 = W2s + k * 8;
#pragma unroll
                for (int f = 0; f < 8; ++f) {
                    float acc = fmaf(hv0, w0[f], a8[f]);
                    acc = fmaf(hv1, w0[8 + f], acc);
                    acc = fmaf(hv2, w0[16 + f], acc);
                    a8[f] = fmaf(hv3, w0[24 + f], acc);
                }
            }
#pragma unroll
            for (int f = 0; f < 8; ++f) a8[f] = valid ? sigmoidf_(a8[f]) : 0.0f;

            const unsigned m = 0xffffffffu;
            int lane = tid & 31;
            int gidx = batch[valid ? v : (N - 1)];
            int gl0  = __shfl_sync(m, gidx, 0);
            bool uni = __all_sync(m, gidx == gl0);
            if (uni) {
#pragma unroll
                for (int f = 0; f < 8; ++f) {
                    float s = a8[f];
                    s += __shfl_xor_sync(m, s, 16);
                    s += __shfl_xor_sync(m, s, 8);
                    s += __shfl_xor_sync(m, s, 4);
                    s += __shfl_xor_sync(m, s, 2);
                    s += __shfl_xor_sync(m, s, 1);
                    if (lane == 0) atomicAdd(&g_Sfv[gl0 * 8 + f], s);
                }
            } else if (valid) {
#pragma unroll
                for (int f = 0; f < 8; ++f) atomicAdd(&g_Sfv[gidx * 8 + f], a8[f]);
            }
        }
        pp ^= 1;
    }
}

// ---------------------------------------------------------------------------
// Edge kernel (R15 config — best measured: 70us)
// ---------------------------------------------------------------------------
__device__ __forceinline__ void edge_reduce_and_store(
    float fe[8], int l, int s, int d, bool active, const float* be2s)
{
    const unsigned fullm = 0xffffffffu;
#pragma unroll
    for (int f = 0; f < 8; ++f)
        fe[f] += __shfl_xor_sync(fullm, fe[f], 8);
    const bool kb2 = (l >> 2) & 1;
    float g4[4];
#pragma unroll
    for (int i = 0; i < 4; ++i) {
        float send = kb2 ? fe[i] : fe[i + 4];
        float recv = __shfl_xor_sync(fullm, send, 4);
        g4[i] = (kb2 ? fe[i + 4] : fe[i]) + recv;
    }
    const bool kb1 = (l >> 1) & 1;
    float g2[2];
#pragma unroll
    for (int i = 0; i < 2; ++i) {
        float send = kb1 ? g4[i] : g4[i + 2];
        float recv = __shfl_xor_sync(fullm, send, 2);
        g2[i] = (kb1 ? g4[i + 2] : g4[i]) + recv;
    }
    const bool kb0 = l & 1;
    float send = kb0 ? g2[0] : g2[1];
    float recv = __shfl_xor_sync(fullm, send, 1);
    float tot = (kb0 ? g2[1] : g2[0]) + recv;
    int c = l & 7;
    int vtx = (l < 8) ? s : d;
    int key = __float_as_int(sigmoidf_(tot + be2s[c]));
    if (active) {
        atomicMin(g_mink + (size_t)vtx * 8 + c, key);
        atomicMax(g_maxk + (size_t)vtx * 8 + c, key);
    }
}

__global__ __launch_bounds__(256, 2) void edge_kernel(
    const float* __restrict__ pos, const int* __restrict__ ei,
    const float* __restrict__ We1, const float* __restrict__ be1,
    const float* __restrict__ We2, const float* __restrict__ be2, int E)
{
    __shared__ __align__(16) float w1l[64];
    __shared__ __align__(16) float be1s[64];
    __shared__ __align__(16) float We2t[512];
    __shared__ float be2s[8];

    const int tid = threadIdx.x;
    for (int i = tid; i < 64; i += 256) { w1l[i] = We1[8192 + i]; be1s[i] = be1[i]; }
    for (int i = tid; i < 512; i += 256) {
        int f = i >> 6, j = i & 63;
        We2t[i] = We2[j * 8 + f];
    }
    if (tid < 8) be2s[tid] = be2[tid];
    __syncthreads();

    const int l  = tid & 15;
    const int j0 = l * 4;
    const int grp = tid >> 4;

    const float4 wl = *reinterpret_cast<const float4*>(w1l + j0);
    const float4 bv = *reinterpret_cast<const float4*>(be1s + j0);

    for (int e0 = blockIdx.x * 64; e0 < E; e0 += gridDim.x * 64) {
        int s[4], d[4];
        bool act[4];
        float dist[4];
        float4 ga[4], gb[4];

#pragma unroll
        for (int b = 0; b < 4; ++b) {
            int e = e0 + b * 16 + grp;
            act[b] = (e < E);
            int ix = act[b] ? e : (E - 1);
            s[b] = ei[ix];
            d[b] = ei[E + ix];
        }
#pragma unroll
        for (int b = 0; b < 4; ++b) {
            ga[b] = *reinterpret_cast<const float4*>(g_xW + (size_t)s[b] * 64 + j0);
            gb[b] = *reinterpret_cast<const float4*>(g_xW + (size_t)d[b] * 64 + j0);
        }
#pragma unroll
        for (int b = 0; b < 4; ++b) {
            float dx = pos[s[b] * 3 + 0] - pos[d[b] * 3 + 0];
            float dy = pos[s[b] * 3 + 1] - pos[d[b] * 3 + 1];
            float dz = pos[s[b] * 3 + 2] - pos[d[b] * 3 + 2];
            dist[b] = sqrtf(dx * dx + dy * dy + dz * dz);
        }

#pragma unroll
        for (int b = 0; b < 4; ++b) {
            float h0 = fmaxf(fmaf(dist[b], wl.x, ga[b].x + gb[b].x) + bv.x, 0.0f);
            float h1 = fmaxf(fmaf(dist[b], wl.y, ga[b].y + gb[b].y) + bv.y, 0.0f);
            float h2 = fmaxf(fmaf(dist[b], wl.z, ga[b].z + gb[b].z) + bv.z, 0.0f);
            float h3 = fmaxf(fmaf(dist[b], wl.w, ga[b].w + gb[b].w) + bv.w, 0.0f);
            float fe[8];
#pragma unroll
            for (int f = 0; f < 8; ++f) {
                float4 w = *reinterpret_cast<const float4*>(We2t + f * 64 + j0);
                float acc = h0 * w.x;
                acc = fmaf(h1, w.y, acc);
                acc = fmaf(h2, w.z, acc);
                fe[f] = fmaf(h3, w.w, acc);
            }
            edge_reduce_and_store(fe, l, s[b], d[b], act[b], be2s);
        }
    }
}

// ---------------------------------------------------------------------------
// Fused per-graph vertex reduce + f1
// ---------------------------------------------------------------------------
__global__ __launch_bounds__(256) void vreduce_f1_kernel(
    const int* __restrict__ vs, const int* __restrict__ es,
    const float* __restrict__ Wd0, const float* __restrict__ bd0,
    const float* __restrict__ Wd1, const float* __restrict__ bd1)
{
    __shared__ float rn[8], rx[8];
    const int tid = threadIdx.x, g = blockIdx.x;
    const int v0 = vs[g], v1 = vs[g + 1];
    if (tid < 8) { rn[tid] = 0.0f; rx[tid] = 0.0f; }
    __syncthreads();

    float ln[8], lx[8];
#pragma unroll
    for (int f = 0; f < 8; ++f) { ln[f] = 0.0f; lx[f] = 0.0f; }
    for (int v = v0 + tid; v < v1; v += 256) {
        const int4* mn = reinterpret_cast<const int4*>(g_mink + (size_t)v * 8);
        const int4* mx = reinterpret_cast<const int4*>(g_maxk + (size_t)v * 8);
        int4 a = mn[0], b = mn[1], c = mx[0], d = mx[1];
        ln[0] += (a.x == 0x7f800000) ? 1.0f : __int_as_float(a.x);
        ln[1] += (a.y == 0x7f800000) ? 1.0f : __int_as_float(a.y);
        ln[2] += (a.z == 0x7f800000) ? 1.0f : __int_as_float(a.z);
        ln[3] += (a.w == 0x7f800000) ? 1.0f : __int_as_float(a.w);
        ln[4] += (b.x == 0x7f800000) ? 1.0f : __int_as_float(b.x);
        ln[5] += (b.y == 0x7f800000) ? 1.0f : __int_as_float(b.y);
        ln[6] += (b.z == 0x7f800000) ? 1.0f : __int_as_float(b.z);
        ln[7] += (b.w == 0x7f800000) ? 1.0f : __int_as_float(b.w);
        lx[0] += (c.x == 0) ? 1.0f : __int_as_float(c.x);
        lx[1] += (c.y == 0) ? 1.0f : __int_as_float(c.y);
        lx[2] += (c.z == 0) ? 1.0f : __int_as_float(c.z);
        lx[3] += (c.w == 0) ? 1.0f : __int_as_float(c.w);
        lx[4] += (d.x == 0) ? 1.0f : __int_as_float(d.x);
        lx[5] += (d.y == 0) ? 1.0f : __int_as_float(d.y);
        lx[6] += (d.z == 0) ? 1.0f : __int_as_float(d.z);
        lx[7] += (d.w == 0) ? 1.0f : __int_as_float(d.w);
    }
    const unsigned m = 0xffffffffu;
    int lane = tid & 31;
#pragma unroll
    for (int f = 0; f < 8; ++f) {
        float s = ln[f];
        s += __shfl_xor_sync(m, s, 16); s += __shfl_xor_sync(m, s, 8);
        s += __shfl_xor_sync(m, s, 4);  s += __shfl_xor_sync(m, s, 2);
        s += __shfl_xor_sync(m, s, 1);
        if (lane == 0) atomicAdd(&rn[f], s);
        float t = lx[f];
        t += __shfl_xor_sync(m, t, 16); t += __shfl_xor_sync(m, t, 8);
        t += __shfl_xor_sync(m, t, 4);  t += __shfl_xor_sync(m, t, 2);
        t += __shfl_xor_sync(m, t, 1);
        if (lane == 0) atomicAdd(&rx[f], t);
    }
    __syncthreads();

    if (tid < 64) {
        int o = tid;
        float a = 0.0f;
#pragma unroll
        for (int f = 0; f < 8; ++f) {
            a = fmaf(g_Sfv[g * 8 + f], Wd0[(4 * f + 1) * 64 + o], a);
            a = fmaf(rx[f],            Wd0[(4 * f + 2) * 64 + o], a);
            a = fmaf(rn[f],            Wd0[(4 * f + 3) * 64 + o], a);
        }
        int nv = v1 - v0;
        int ne = es[g + 1] - es[g];
        float x0 = a / (float)nv + bd0[o];
        float x1 = (ne - (nv - 1) > 0)
                       ? (Wd1[64 + o] + Wd1[128 + o] + Wd1[192 + o] + bd1[o])
                       : 0.0f;
        g_h[g * 64 + o] = x0 + x1;
    }
}

// ---------------------------------------------------------------------------
// Fused BN + out MLP: each block redundantly computes batch stats over g_h
// (L2-resident, cheap), then normalizes its 16 graphs and runs the MLP.
// ---------------------------------------------------------------------------
__global__ __launch_bounds__(1024) void out_kernel(
    const float* __restrict__ gamma, const float* __restrict__ beta,
    const float* __restrict__ Wo1, const float* __restrict__ bo1,
    const float* __restrict__ Wo2, const float* __restrict__ bo2,
    float* __restrict__ out, int G)
{
    __shared__ float ps[1024];
    __shared__ float mu_s[64];
    __shared__ float rs_s[64];
    __shared__ float hn[16][64];
    __shared__ float t1[16][64];

    int t = threadIdx.x, o = t & 63, grp16 = t >> 6;   // 16 groups of 64

    // pass 1: mean
    float s = 0.0f;
    for (int r = grp16; r < G; r += 16) s += g_h[r * 64 + o];
    ps[t] = s;
    __syncthreads();
    if (t < 64) {
        float S = 0.0f;
#pragma unroll
        for (int k = 0; k < 16; ++k) S += ps[k * 64 + o];
        mu_s[o] = S / (float)G;
    }
    __syncthreads();
    float mu = mu_s[o];
    // pass 2: var
    s = 0.0f;
    for (int r = grp16; r < G; r += 16) {
        float dv = g_h[r * 64 + o] - mu;
        s = fmaf(dv, dv, s);
    }
    ps[t] = s;
    __syncthreads();
    if (t < 64) {
        float S = 0.0f;
#pragma unroll
        for (int k = 0; k < 16; ++k) S += ps[k * 64 + o];
        rs_s[o] = rsqrtf(S / (float)G + 1e-5f);
    }
    __syncthreads();

    int g = blockIdx.x * 16 + grp16;
    float v = 0.0f;
    if (g < G) v = (g_h[g * 64 + o] - mu_s[o]) * rs_s[o] * gamma[o] + beta[o];
    hn[grp16][o] = v;
    __syncthreads();
    float a = bo1[o];
#pragma unroll 8
    for (int k = 0; k < 64; ++k) a = fmaf(hn[grp16][k], Wo1[k * 64 + o], a);
    t1[grp16][o] = fmaxf(a, 0.0f);
    __syncthreads();
    float b = bo2[o];
#pragma unroll 8
    for (int k = 0; k < 64; ++k) b = fmaf(t1[grp16][k], Wo2[k * 64 + o], b);
    if (g < G) out[g * 64 + o] = b;
}

extern "C" void kernel_launch(void* const* d_in, const int* in_sizes, int n_in,
                              void* d_out, int out_size)
{
    const float* x     = (const float*)d_in[0];
    const float* pos   = (const float*)d_in[1];
    const int*   ei    = (const int*)d_in[2];
    const int*   vs    = (const int*)d_in[3];
    const int*   es    = (const int*)d_in[4];
    const int*   batch = (const int*)d_in[5];
    const float* W1  = (const float*)d_in[6];
    const float* b1  = (const float*)d_in[7];
    const float* W2  = (const float*)d_in[8];
    const float* b2  = (const float*)d_in[9];
    const float* We1 = (const float*)d_in[10];
    const float* be1 = (const float*)d_in[11];
    const float* We2 = (const float*)d_in[12];
    const float* be2 = (const float*)d_in[13];
    const float* Wd0 = (const float*)d_in[14];
    const float* bd0 = (const float*)d_in[15];
    const float* Wd1 = (const float*)d_in[16];
    const float* bd1 = (const float*)d_in[17];
    const float* gm  = (const float*)d_in[18];
    const float* bt  = (const float*)d_in[19];
    const float* Wo1 = (const float*)d_in[20];
    const float* bo1 = (const float*)d_in[21];
    const float* Wo2 = (const float*)d_in[22];
    const float* bo2 = (const float*)d_in[23];

    int N = in_sizes[0] / 128;
    int E = in_sizes[2] / 2;
    int G = out_size / 64;
    int tiles = (N + 127) / 128;

    init_kernel<<<(N * 2 + 255) / 256, 256>>>(N * 2, G * 8);

    size_t smv = (size_t)SMV_FLOATS * sizeof(float);
    cudaFuncSetAttribute(vertex_kernel, cudaFuncAttributeMaxDynamicSharedMemorySize, (int)smv);
    vertex_kernel<<<148, 512, smv>>>(x, batch, W1, b1, W2, b2, We1, N, tiles);

    edge_kernel<<<2048, 256>>>(pos, ei, We1, be1, We2, be2, E);
    vreduce_f1_kernel<<<G, 256>>>(vs, es, Wd0, bd0, Wd1, bd1);
    out_kernel<<<(G + 15) / 16, 1024>>>(gm, bt, Wo1, bo1, Wo2, bo2, (float*)d_out, G);
}